// round 9
// baseline (speedup 1.0000x reference)
#include <cuda_runtime.h>
#include <stdint.h>
#include <math.h>

// Problem constants
#define S_LEN   2048
#define H_DIM   4096
#define NHEADS  32
#define HD      128
#define K3      12288            // 3*H
#define INV_NORM 0.08838834764831845f   // 1/sqrt(128)

typedef unsigned int u32;

// Scratch (device globals: allocation-free)
__device__ float g_fused[(size_t)S_LEN * K3];   // [S, NH, 3, HD]
__device__ float g_ctx[(size_t)S_LEN * H_DIM];  // [S, H]

// ---------------------------------------------------------------------------
// tf32 tensor-core GEMM: C[M,N] = A[M,K] @ Bw[N,K]^T + bias[N] (+ resid)
// CTA tile 128x256, BK=32, 256 threads (8 warps), warp tile 64x64.
// cp.async double-buffered raw-fp32 smem; tf32 cvt at fragment load.
// ---------------------------------------------------------------------------
#define BM 128
#define BN 256
#define BK 32
#define SPITCH 36                  // bank = (4*row + col) % 32 -> conflict-free
#define AWORDS (BM * SPITCH)       // 4608
#define BWORDS (BN * SPITCH)       // 9216
#define GEMM_SMEM (2 * (AWORDS + BWORDS) * 4)   // 110592 B

__device__ __forceinline__ u32 f2tf32(float x) {
    u32 r;
    asm("cvt.rna.tf32.f32 %0, %1;" : "=r"(r) : "f"(x));
    return r;
}

__device__ __forceinline__ void mma_tf32(float c[4], const u32 a[4],
                                         const u32 b[2]) {
    asm volatile(
        "mma.sync.aligned.m16n8k8.row.col.f32.tf32.tf32.f32 "
        "{%0,%1,%2,%3}, {%4,%5,%6,%7}, {%8,%9}, {%0,%1,%2,%3};"
        : "+f"(c[0]), "+f"(c[1]), "+f"(c[2]), "+f"(c[3])
        : "r"(a[0]), "r"(a[1]), "r"(a[2]), "r"(a[3]), "r"(b[0]), "r"(b[1]));
}

__device__ __forceinline__ void cpasync16(float* dst_smem, const float* src) {
    u32 sd = (u32)__cvta_generic_to_shared(dst_smem);
    asm volatile("cp.async.cg.shared.global [%0], [%1], 16;"
                 :: "r"(sd), "l"(src));
}

template<bool ADD_RES>
__global__ __launch_bounds__(256, 1) void gemm_tf32(
    const float* __restrict__ A, const float* __restrict__ Bw,
    const float* __restrict__ bias, const float* __restrict__ resid,
    float* __restrict__ C, int M, int N, int K)
{
    extern __shared__ float sm[];
    float* Abuf[2] = { sm,               sm + AWORDS };
    float* Bbuf[2] = { sm + 2 * AWORDS,  sm + 2 * AWORDS + BWORDS };

    const int tid  = threadIdx.x;
    const int warp = tid >> 5;
    const int lane = tid & 31;
    const int wm   = (warp & 1) * 64;    // 2 warps in M
    const int wn   = (warp >> 1) * 64;   // 4 warps in N

    const float* Ab = A  + (size_t)blockIdx.y * BM * K;
    const float* Bb = Bw + (size_t)blockIdx.x * BN * K;

    float acc[4][8][4];
#pragma unroll
    for (int i = 0; i < 4; i++)
#pragma unroll
        for (int j = 0; j < 8; j++)
#pragma unroll
            for (int r = 0; r < 4; r++) acc[i][j][r] = 0.f;

    // Fill helper indices: A = 1024 float4s (4/thread), B = 2048 (8/thread)
    // idx -> row = idx>>3, col4 = (idx&7)*4
    // Prologue: tile 0 into buffer 0
#pragma unroll
    for (int i = 0; i < 4; i++) {
        const int idx = tid + i * 256;
        const int row = idx >> 3, c4 = (idx & 7) * 4;
        cpasync16(&Abuf[0][row * SPITCH + c4], Ab + (size_t)row * K + c4);
    }
#pragma unroll
    for (int i = 0; i < 8; i++) {
        const int idx = tid + i * 256;
        const int row = idx >> 3, c4 = (idx & 7) * 4;
        cpasync16(&Bbuf[0][row * SPITCH + c4], Bb + (size_t)row * K + c4);
    }
    asm volatile("cp.async.commit_group;");
    asm volatile("cp.async.wait_group 0;");
    __syncthreads();

    const int NT = K / BK;
    for (int t = 0; t < NT; t++) {
        const int buf = t & 1;
        if (t + 1 < NT) {
            const int nxt = buf ^ 1;
            const int koff = (t + 1) * BK;
#pragma unroll
            for (int i = 0; i < 4; i++) {
                const int idx = tid + i * 256;
                const int row = idx >> 3, c4 = (idx & 7) * 4;
                cpasync16(&Abuf[nxt][row * SPITCH + c4],
                          Ab + (size_t)row * K + koff + c4);
            }
#pragma unroll
            for (int i = 0; i < 8; i++) {
                const int idx = tid + i * 256;
                const int row = idx >> 3, c4 = (idx & 7) * 4;
                cpasync16(&Bbuf[nxt][row * SPITCH + c4],
                          Bb + (size_t)row * K + koff + c4);
            }
        }
        asm volatile("cp.async.commit_group;");

        const float* As = Abuf[buf];
        const float* Bs = Bbuf[buf];

#pragma unroll
        for (int kk = 0; kk < BK; kk += 8) {
            u32 af[4][4], bf[8][2];
            const int kq = kk + (lane & 3);
#pragma unroll
            for (int mf = 0; mf < 4; mf++) {
                const int r0 = wm + mf * 16 + (lane >> 2);
                af[mf][0] = f2tf32(As[r0 * SPITCH + kq]);
                af[mf][1] = f2tf32(As[(r0 + 8) * SPITCH + kq]);
                af[mf][2] = f2tf32(As[r0 * SPITCH + kq + 4]);
                af[mf][3] = f2tf32(As[(r0 + 8) * SPITCH + kq + 4]);
            }
#pragma unroll
            for (int nf = 0; nf < 8; nf++) {
                const int c0 = wn + nf * 8 + (lane >> 2);
                bf[nf][0] = f2tf32(Bs[c0 * SPITCH + kq]);
                bf[nf][1] = f2tf32(Bs[c0 * SPITCH + kq + 4]);
            }
#pragma unroll
            for (int mf = 0; mf < 4; mf++)
#pragma unroll
                for (int nf = 0; nf < 8; nf++)
                    mma_tf32(acc[mf][nf], af[mf], bf[nf]);
        }

        asm volatile("cp.async.wait_group 0;");
        __syncthreads();
    }

    // Epilogue
#pragma unroll
    for (int mf = 0; mf < 4; mf++) {
        const int row = blockIdx.y * BM + wm + mf * 16 + (lane >> 2);
#pragma unroll
        for (int nf = 0; nf < 8; nf++) {
            const int col = blockIdx.x * BN + wn + nf * 8 + 2 * (lane & 3);
            const float b0 = bias[col], b1 = bias[col + 1];
            float v0 = acc[mf][nf][0] + b0;
            float v1 = acc[mf][nf][1] + b1;
            float v2 = acc[mf][nf][2] + b0;
            float v3 = acc[mf][nf][3] + b1;
            if (ADD_RES) {
                v0 += resid[(size_t)row * N + col];
                v1 += resid[(size_t)row * N + col + 1];
                v2 += resid[(size_t)(row + 8) * N + col];
                v3 += resid[(size_t)(row + 8) * N + col + 1];
            }
            *(float2*)(C + (size_t)row * N + col)       = make_float2(v0, v1);
            *(float2*)(C + (size_t)(row + 8) * N + col) = make_float2(v2, v3);
        }
    }
}

// ---------------------------------------------------------------------------
// Flash attention (fp32, causal + alibi), unchanged (passing since R1).
// ---------------------------------------------------------------------------
#define AQ  64
#define AKV 64
#define QP  132
#define SP  68
#define NEG_INF -1e30f
#define ATTN_SMEM ((AQ*QP + 2*AKV*QP + AQ*SP) * 4)

__global__ __launch_bounds__(256) void attn_kernel(const float* __restrict__ alibi)
{
    extern __shared__ float smref[];
    float* Qs = smref;
    float* Ks = Qs + AQ * QP;
    float* Vs = Ks + AKV * QP;
    float* Sc = Vs + AKV * QP;

    const int q0  = blockIdx.x * AQ;
    const int h   = blockIdx.y;
    const int tid = threadIdx.x;
    const int tr  = tid >> 4;
    const int tc  = tid & 15;

    {
        const float* qbase = g_fused + (size_t)q0 * K3 + h * 384;
        for (int idx = tid; idx < AQ * 32; idx += 256) {
            const int r  = idx >> 5;
            const int c4 = (idx & 31) << 2;
            *(float4*)(Qs + r * QP + c4) =
                *(const float4*)(qbase + (size_t)r * K3 + c4);
        }
    }

    float m_i[4], l_i[4], o[4][8];
#pragma unroll
    for (int i = 0; i < 4; i++) {
        m_i[i] = NEG_INF; l_i[i] = 0.f;
#pragma unroll
        for (int d = 0; d < 8; d++) o[i][d] = 0.f;
    }

    const float* alibi_h = alibi + (size_t)h * S_LEN;
    const int nkt = (q0 / AKV) + 1;

    for (int kt = 0; kt < nkt; kt++) {
        const int kc = kt * AKV;
        {
            const float* kbase = g_fused + (size_t)kc * K3 + h * 384 + 128;
            const float* vbase = kbase + 128;
            for (int idx = tid; idx < AKV * 32; idx += 256) {
                const int r  = idx >> 5;
                const int c4 = (idx & 31) << 2;
                *(float4*)(Ks + r * QP + c4) =
                    *(const float4*)(kbase + (size_t)r * K3 + c4);
                *(float4*)(Vs + r * QP + c4) =
                    *(const float4*)(vbase + (size_t)r * K3 + c4);
            }
        }
        __syncthreads();

        float acc[4][4];
#pragma unroll
        for (int i = 0; i < 4; i++)
#pragma unroll
            for (int j = 0; j < 4; j++) acc[i][j] = 0.f;

#pragma unroll 8
        for (int k = 0; k < HD; k += 4) {
            float4 qv[4], kv[4];
#pragma unroll
            for (int i = 0; i < 4; i++)
                qv[i] = *(const float4*)(Qs + (tr + 16 * i) * QP + k);
#pragma unroll
            for (int j = 0; j < 4; j++)
                kv[j] = *(const float4*)(Ks + (tc + 16 * j) * QP + k);
#pragma unroll
            for (int i = 0; i < 4; i++)
#pragma unroll
                for (int j = 0; j < 4; j++) {
                    acc[i][j] += qv[i].x * kv[j].x;
                    acc[i][j] += qv[i].y * kv[j].y;
                    acc[i][j] += qv[i].z * kv[j].z;
                    acc[i][j] += qv[i].w * kv[j].w;
                }
        }

#pragma unroll
        for (int i = 0; i < 4; i++) {
            const int r = q0 + tr + 16 * i;
            float s[4];
            float mx = NEG_INF;
#pragma unroll
            for (int j = 0; j < 4; j++) {
                const int c = kc + tc + 16 * j;
                s[j] = (c <= r) ? acc[i][j] * INV_NORM + __ldg(&alibi_h[c])
                                : NEG_INF;
                mx = fmaxf(mx, s[j]);
            }
            mx = fmaxf(mx, __shfl_xor_sync(0xffffffffu, mx, 1));
            mx = fmaxf(mx, __shfl_xor_sync(0xffffffffu, mx, 2));
            mx = fmaxf(mx, __shfl_xor_sync(0xffffffffu, mx, 4));
            mx = fmaxf(mx, __shfl_xor_sync(0xffffffffu, mx, 8));

            const float m_new = fmaxf(m_i[i], mx);
            const float scale = __expf(m_i[i] - m_new);
            m_i[i] = m_new;

            float ps = 0.f;
#pragma unroll
            for (int j = 0; j < 4; j++) {
                const float p = __expf(s[j] - m_new);
                Sc[(tr + 16 * i) * SP + tc + 16 * j] = p;
                ps += p;
            }
            ps += __shfl_xor_sync(0xffffffffu, ps, 1);
            ps += __shfl_xor_sync(0xffffffffu, ps, 2);
            ps += __shfl_xor_sync(0xffffffffu, ps, 4);
            ps += __shfl_xor_sync(0xffffffffu, ps, 8);

            l_i[i] = l_i[i] * scale + ps;
#pragma unroll
            for (int d = 0; d < 8; d++) o[i][d] *= scale;
        }
        __syncthreads();

#pragma unroll 4
        for (int c = 0; c < AKV; c++) {
            const float4 v0 = *(const float4*)(Vs + c * QP + tc * 8);
            const float4 v1 = *(const float4*)(Vs + c * QP + tc * 8 + 4);
#pragma unroll
            for (int i = 0; i < 4; i++) {
                const float p = Sc[(tr + 16 * i) * SP + c];
                o[i][0] += p * v0.x; o[i][1] += p * v0.y;
                o[i][2] += p * v0.z; o[i][3] += p * v0.w;
                o[i][4] += p * v1.x; o[i][5] += p * v1.y;
                o[i][6] += p * v1.z; o[i][7] += p * v1.w;
            }
        }
        __syncthreads();
    }

#pragma unroll
    for (int i = 0; i < 4; i++) {
        const int r = q0 + tr + 16 * i;
        const float inv = 1.0f / l_i[i];
        float4 w0 = make_float4(o[i][0] * inv, o[i][1] * inv,
                                o[i][2] * inv, o[i][3] * inv);
        float4 w1 = make_float4(o[i][4] * inv, o[i][5] * inv,
                                o[i][6] * inv, o[i][7] * inv);
        float* dst = g_ctx + (size_t)r * H_DIM + h * HD + tc * 8;
        *(float4*)dst = w0;
        *(float4*)(dst + 4) = w1;
    }
}

// ---------------------------------------------------------------------------
extern "C" void kernel_launch(void* const* d_in, const int* in_sizes, int n_in,
                              void* d_out, int out_size)
{
    const float* hidden  = (const float*)d_in[0];
    const float* resid   = (const float*)d_in[1];
    const float* alibi   = (const float*)d_in[2];
    const float* qkv_w   = (const float*)d_in[4];
    const float* qkv_b   = (const float*)d_in[5];
    const float* dense_w = (const float*)d_in[6];
    const float* dense_b = (const float*)d_in[7];
    float* out = (float*)d_out;

    float *fused_p, *ctx_p;
    cudaGetSymbolAddress((void**)&fused_p, g_fused);
    cudaGetSymbolAddress((void**)&ctx_p, g_ctx);

    cudaFuncSetAttribute(gemm_tf32<false>,
                         cudaFuncAttributeMaxDynamicSharedMemorySize, GEMM_SMEM);
    cudaFuncSetAttribute(gemm_tf32<true>,
                         cudaFuncAttributeMaxDynamicSharedMemorySize, GEMM_SMEM);
    cudaFuncSetAttribute(attn_kernel,
                         cudaFuncAttributeMaxDynamicSharedMemorySize, ATTN_SMEM);

    // 1) fused = hidden @ qkv_w^T + qkv_b   [2048, 12288]
    gemm_tf32<false><<<dim3(K3 / BN, S_LEN / BM), 256, GEMM_SMEM>>>(
        hidden, qkv_w, qkv_b, nullptr, fused_p, S_LEN, K3, H_DIM);

    // 2) attention -> g_ctx [2048, 4096]
    attn_kernel<<<dim3(S_LEN / AQ, NHEADS), 256, ATTN_SMEM>>>(alibi);

    // 3) out = ctx @ dense_w^T + dense_b + residual
    gemm_tf32<true><<<dim3(H_DIM / BN, S_LEN / BM), 256, GEMM_SMEM>>>(
        ctx_p, dense_w, dense_b, resid, out, S_LEN, H_DIM, H_DIM);
}

// round 10
// speedup vs baseline: 1.4288x; 1.4288x over previous
#include <cuda_runtime.h>
#include <stdint.h>
#include <math.h>

// Problem constants
#define S_LEN   2048
#define H_DIM   4096
#define NHEADS  32
#define HD      128
#define K3      12288            // 3*H
#define INV_NORM 0.08838834764831845f   // 1/sqrt(128)

typedef unsigned int u32;

// Scratch (device globals: allocation-free)
__device__ float g_fused[(size_t)S_LEN * K3];   // [S, NH, 3, HD]
__device__ float g_ctx[(size_t)S_LEN * H_DIM];  // [S, H]

// ---------------------------------------------------------------------------
// Common tensor-core helpers (tf32 m16n8k8)
// ---------------------------------------------------------------------------
__device__ __forceinline__ u32 f2tf32(float x) {
    u32 r;
    asm("cvt.rna.tf32.f32 %0, %1;" : "=r"(r) : "f"(x));
    return r;
}

__device__ __forceinline__ void mma_tf32(float c[4], const u32 a[4],
                                         const u32 b[2]) {
    asm volatile(
        "mma.sync.aligned.m16n8k8.row.col.f32.tf32.tf32.f32 "
        "{%0,%1,%2,%3}, {%4,%5,%6,%7}, {%8,%9}, {%0,%1,%2,%3};"
        : "+f"(c[0]), "+f"(c[1]), "+f"(c[2]), "+f"(c[3])
        : "r"(a[0]), "r"(a[1]), "r"(a[2]), "r"(a[3]), "r"(b[0]), "r"(b[1]));
}

__device__ __forceinline__ void cpasync16(float* dst_smem, const float* src) {
    u32 sd = (u32)__cvta_generic_to_shared(dst_smem);
    asm volatile("cp.async.cg.shared.global [%0], [%1], 16;"
                 :: "r"(sd), "l"(src));
}

// ---------------------------------------------------------------------------
// tf32 tensor-core GEMM (R7 config: best known): C = A @ Bw^T + bias (+resid)
// 128x128x32 tile, 256 threads, warp tile 64x32, cp.async double buffer.
// ---------------------------------------------------------------------------
#define BM 128
#define BN 128
#define BK 32
#define SPITCH 36
#define TILE_WORDS (BM * SPITCH)
#define GEMM_SMEM (4 * TILE_WORDS * 4)   // 73728 B

template<bool ADD_RES>
__global__ __launch_bounds__(256, 2) void gemm_tf32(
    const float* __restrict__ A, const float* __restrict__ Bw,
    const float* __restrict__ bias, const float* __restrict__ resid,
    float* __restrict__ C, int M, int N, int K)
{
    extern __shared__ float sm[];
    float* Abuf[2] = { sm,                  sm + TILE_WORDS };
    float* Bbuf[2] = { sm + 2 * TILE_WORDS, sm + 3 * TILE_WORDS };

    const int tid  = threadIdx.x;
    const int warp = tid >> 5;
    const int lane = tid & 31;
    const int wm   = (warp & 1) * 64;
    const int wn   = (warp >> 1) * 32;
    const int lr   = tid >> 3;
    const int lc   = (tid & 7) * 4;

    const float* Ab = A  + (size_t)blockIdx.y * BM * K;
    const float* Bb = Bw + (size_t)blockIdx.x * BN * K;

    float acc[4][4][4];
#pragma unroll
    for (int i = 0; i < 4; i++)
#pragma unroll
        for (int j = 0; j < 4; j++)
#pragma unroll
            for (int r = 0; r < 4; r++) acc[i][j][r] = 0.f;

#pragma unroll
    for (int i = 0; i < 4; i++) {
        const int row = lr + i * 32;
        cpasync16(&Abuf[0][row * SPITCH + lc], Ab + (size_t)row * K + lc);
        cpasync16(&Bbuf[0][row * SPITCH + lc], Bb + (size_t)row * K + lc);
    }
    asm volatile("cp.async.commit_group;");
    asm volatile("cp.async.wait_group 0;");
    __syncthreads();

    const int NT = K / BK;
    for (int t = 0; t < NT; t++) {
        const int buf = t & 1;
        if (t + 1 < NT) {
            const int nxt = buf ^ 1;
            const int koff = (t + 1) * BK;
#pragma unroll
            for (int i = 0; i < 4; i++) {
                const int row = lr + i * 32;
                cpasync16(&Abuf[nxt][row * SPITCH + lc],
                          Ab + (size_t)row * K + koff + lc);
                cpasync16(&Bbuf[nxt][row * SPITCH + lc],
                          Bb + (size_t)row * K + koff + lc);
            }
        }
        asm volatile("cp.async.commit_group;");

        const float* As = Abuf[buf];
        const float* Bs = Bbuf[buf];

#pragma unroll
        for (int kk = 0; kk < BK; kk += 8) {
            u32 af[4][4], bf[4][2];
            const int kq = kk + (lane & 3);
#pragma unroll
            for (int mf = 0; mf < 4; mf++) {
                const int r0 = wm + mf * 16 + (lane >> 2);
                af[mf][0] = f2tf32(As[r0 * SPITCH + kq]);
                af[mf][1] = f2tf32(As[(r0 + 8) * SPITCH + kq]);
                af[mf][2] = f2tf32(As[r0 * SPITCH + kq + 4]);
                af[mf][3] = f2tf32(As[(r0 + 8) * SPITCH + kq + 4]);
            }
#pragma unroll
            for (int nf = 0; nf < 4; nf++) {
                const int c0 = wn + nf * 8 + (lane >> 2);
                bf[nf][0] = f2tf32(Bs[c0 * SPITCH + kq]);
                bf[nf][1] = f2tf32(Bs[c0 * SPITCH + kq + 4]);
            }
#pragma unroll
            for (int mf = 0; mf < 4; mf++)
#pragma unroll
                for (int nf = 0; nf < 4; nf++)
                    mma_tf32(acc[mf][nf], af[mf], bf[nf]);
        }

        asm volatile("cp.async.wait_group 0;");
        __syncthreads();
    }

#pragma unroll
    for (int mf = 0; mf < 4; mf++) {
        const int row = blockIdx.y * BM + wm + mf * 16 + (lane >> 2);
#pragma unroll
        for (int nf = 0; nf < 4; nf++) {
            const int col = blockIdx.x * BN + wn + nf * 8 + 2 * (lane & 3);
            const float b0 = bias[col], b1 = bias[col + 1];
            float v0 = acc[mf][nf][0] + b0;
            float v1 = acc[mf][nf][1] + b1;
            float v2 = acc[mf][nf][2] + b0;
            float v3 = acc[mf][nf][3] + b1;
            if (ADD_RES) {
                v0 += resid[(size_t)row * N + col];
                v1 += resid[(size_t)row * N + col + 1];
                v2 += resid[(size_t)(row + 8) * N + col];
                v3 += resid[(size_t)(row + 8) * N + col + 1];
            }
            *(float2*)(C + (size_t)row * N + col)       = make_float2(v0, v1);
            *(float2*)(C + (size_t)(row + 8) * N + col) = make_float2(v2, v3);
        }
    }
}

// ---------------------------------------------------------------------------
// Tensor-core flash attention (tf32 mma, fp32 softmax, causal + alibi)
// CTA: 128 q-rows x 64-kv tiles, 8 warps (warp = 16 q-rows, full 64 kv cols).
// ---------------------------------------------------------------------------
#define AQM 128
#define AKT 64
#define QPITCH 132                 // (4*row + col) % 32 distinct -> conflict-free
#define SCP 68
#define NEG_INF -1e30f
#define ATTN_SMEM ((AQM*QPITCH + 2*AKT*QPITCH + AQM*SCP + S_LEN) * 4)  // 178176

__global__ __launch_bounds__(256, 1) void attn_mma(const float* __restrict__ alibi)
{
    extern __shared__ float sm[];
    float* Qs  = sm;                        // [128][132] raw fp32
    float* Ks  = Qs + AQM * QPITCH;         // [64][132]
    float* Vs  = Ks + AKT * QPITCH;         // [64][132]
    float* Sc  = Vs + AKT * QPITCH;         // [128][68]  probs (fp32)
    float* sal = Sc + AQM * SCP;            // [2048] alibi row

    const int qt   = (int)gridDim.x - 1 - (int)blockIdx.x;  // heavy tiles first
    const int q0   = qt * AQM;
    const int h    = blockIdx.y;
    const int tid  = threadIdx.x;
    const int w    = tid >> 5;
    const int lane = tid & 31;
    const int g    = lane >> 2;   // 0..7
    const int q4   = lane & 3;    // 0..3

    // Load Q tile (128 x 128 fp32)
    {
        const float* qbase = g_fused + (size_t)q0 * K3 + h * 384;
#pragma unroll
        for (int i = 0; i < 16; i++) {
            const int idx = tid + i * 256;
            const int r = idx >> 5, c4 = (idx & 31) * 4;
            *(float4*)(Qs + r * QPITCH + c4) =
                *(const float4*)(qbase + (size_t)r * K3 + c4);
        }
        const float* alibi_h = alibi + (size_t)h * S_LEN;
        for (int idx = tid; idx < q0 + AQM; idx += 256)
            sal[idx] = alibi_h[idx];
    }

    const int r0loc = w * 16 + g;          // warp-local first row
    const int gr0 = q0 + r0loc;
    const int gr1 = gr0 + 8;

    float o[16][4];
#pragma unroll
    for (int nf = 0; nf < 16; nf++)
#pragma unroll
        for (int r = 0; r < 4; r++) o[nf][r] = 0.f;
    float m0 = NEG_INF, m1 = NEG_INF, l0 = 0.f, l1 = 0.f;

    const int nkt = q0 / AKT + 2;
    for (int kt = 0; kt < nkt; kt++) {
        const int kc = kt * AKT;
        // Fill K/V (64 x 128 each) via cp.async
        {
            const float* kb = g_fused + (size_t)kc * K3 + h * 384 + 128;
#pragma unroll
            for (int i = 0; i < 8; i++) {
                const int idx = tid + i * 256;
                const int r = idx >> 5, c4 = (idx & 31) * 4;
                cpasync16(Ks + r * QPITCH + c4, kb + (size_t)r * K3 + c4);
                cpasync16(Vs + r * QPITCH + c4, kb + (size_t)r * K3 + 128 + c4);
            }
        }
        asm volatile("cp.async.commit_group;");
        asm volatile("cp.async.wait_group 0;");
        __syncthreads();

        // S = Q K^T  (warp: 16 rows x 64 cols, k = 128)
        float sacc[8][4];
#pragma unroll
        for (int nf = 0; nf < 8; nf++)
#pragma unroll
            for (int r = 0; r < 4; r++) sacc[nf][r] = 0.f;

#pragma unroll
        for (int kk = 0; kk < 16; kk++) {
            const int kq = kk * 8 + q4;
            u32 af[4];
            af[0] = f2tf32(Qs[r0loc * QPITCH + kq]);
            af[1] = f2tf32(Qs[(r0loc + 8) * QPITCH + kq]);
            af[2] = f2tf32(Qs[r0loc * QPITCH + kq + 4]);
            af[3] = f2tf32(Qs[(r0loc + 8) * QPITCH + kq + 4]);
#pragma unroll
            for (int nf = 0; nf < 8; nf++) {
                const int c0 = nf * 8 + g;
                u32 bf[2];
                bf[0] = f2tf32(Ks[c0 * QPITCH + kq]);
                bf[1] = f2tf32(Ks[c0 * QPITCH + kq + 4]);
                mma_tf32(sacc[nf], af, bf);
            }
        }

        // Online softmax (rows gr0 / gr1), fp32
        float mx0 = NEG_INF, mx1 = NEG_INF;
#pragma unroll
        for (int nf = 0; nf < 8; nf++) {
            const int j0 = kc + nf * 8 + 2 * q4;
            const float a0 = sal[j0], a1 = sal[j0 + 1];
            const float s0 = (j0     <= gr0) ? sacc[nf][0] * INV_NORM + a0 : NEG_INF;
            const float s1 = (j0 + 1 <= gr0) ? sacc[nf][1] * INV_NORM + a1 : NEG_INF;
            const float s2 = (j0     <= gr1) ? sacc[nf][2] * INV_NORM + a0 : NEG_INF;
            const float s3 = (j0 + 1 <= gr1) ? sacc[nf][3] * INV_NORM + a1 : NEG_INF;
            sacc[nf][0] = s0; sacc[nf][1] = s1;
            sacc[nf][2] = s2; sacc[nf][3] = s3;
            mx0 = fmaxf(mx0, fmaxf(s0, s1));
            mx1 = fmaxf(mx1, fmaxf(s2, s3));
        }
        mx0 = fmaxf(mx0, __shfl_xor_sync(0xffffffffu, mx0, 1));
        mx0 = fmaxf(mx0, __shfl_xor_sync(0xffffffffu, mx0, 2));
        mx1 = fmaxf(mx1, __shfl_xor_sync(0xffffffffu, mx1, 1));
        mx1 = fmaxf(mx1, __shfl_xor_sync(0xffffffffu, mx1, 2));

        const float mn0 = fmaxf(m0, mx0), mn1 = fmaxf(m1, mx1);
        const float sc0 = __expf(m0 - mn0), sc1 = __expf(m1 - mn1);
        m0 = mn0; m1 = mn1;

        float ps0 = 0.f, ps1 = 0.f;
#pragma unroll
        for (int nf = 0; nf < 8; nf++) {
            const float p0 = __expf(sacc[nf][0] - mn0);
            const float p1 = __expf(sacc[nf][1] - mn0);
            const float p2 = __expf(sacc[nf][2] - mn1);
            const float p3 = __expf(sacc[nf][3] - mn1);
            ps0 += p0 + p1; ps1 += p2 + p3;
            const int cj = nf * 8 + 2 * q4;
            *(float2*)(Sc + r0loc * SCP + cj)       = make_float2(p0, p1);
            *(float2*)(Sc + (r0loc + 8) * SCP + cj) = make_float2(p2, p3);
        }
        ps0 += __shfl_xor_sync(0xffffffffu, ps0, 1);
        ps0 += __shfl_xor_sync(0xffffffffu, ps0, 2);
        ps1 += __shfl_xor_sync(0xffffffffu, ps1, 1);
        ps1 += __shfl_xor_sync(0xffffffffu, ps1, 2);
        l0 = l0 * sc0 + ps0;
        l1 = l1 * sc1 + ps1;

#pragma unroll
        for (int nf = 0; nf < 16; nf++) {
            o[nf][0] *= sc0; o[nf][1] *= sc0;
            o[nf][2] *= sc1; o[nf][3] *= sc1;
        }
        __syncwarp();   // order P stores before frag reloads (warp-private rows)

        // O += P V  (warp: 16 rows x 128 cols, k = 64)
#pragma unroll
        for (int kk = 0; kk < 8; kk++) {
            const int kq = kk * 8 + q4;
            u32 af[4];
            af[0] = f2tf32(Sc[r0loc * SCP + kq]);
            af[1] = f2tf32(Sc[(r0loc + 8) * SCP + kq]);
            af[2] = f2tf32(Sc[r0loc * SCP + kq + 4]);
            af[3] = f2tf32(Sc[(r0loc + 8) * SCP + kq + 4]);
#pragma unroll
            for (int nf = 0; nf < 16; nf++) {
                const int d = nf * 8 + g;
                u32 bf[2];
                bf[0] = f2tf32(Vs[kq * QPITCH + d]);
                bf[1] = f2tf32(Vs[(kq + 4) * QPITCH + d]);
                mma_tf32(o[nf], af, bf);
            }
        }
        __syncthreads();   // all reads done before next K/V fill
    }

    // Normalize + write ctx
    const float inv0 = 1.f / l0, inv1 = 1.f / l1;
    float* dst0 = g_ctx + (size_t)gr0 * H_DIM + h * HD;
    float* dst1 = g_ctx + (size_t)gr1 * H_DIM + h * HD;
#pragma unroll
    for (int nf = 0; nf < 16; nf++) {
        const int d = nf * 8 + 2 * q4;
        *(float2*)(dst0 + d) = make_float2(o[nf][0] * inv0, o[nf][1] * inv0);
        *(float2*)(dst1 + d) = make_float2(o[nf][2] * inv1, o[nf][3] * inv1);
    }
}

// ---------------------------------------------------------------------------
extern "C" void kernel_launch(void* const* d_in, const int* in_sizes, int n_in,
                              void* d_out, int out_size)
{
    const float* hidden  = (const float*)d_in[0];
    const float* resid   = (const float*)d_in[1];
    const float* alibi   = (const float*)d_in[2];
    const float* qkv_w   = (const float*)d_in[4];
    const float* qkv_b   = (const float*)d_in[5];
    const float* dense_w = (const float*)d_in[6];
    const float* dense_b = (const float*)d_in[7];
    float* out = (float*)d_out;

    float *fused_p, *ctx_p;
    cudaGetSymbolAddress((void**)&fused_p, g_fused);
    cudaGetSymbolAddress((void**)&ctx_p, g_ctx);

    cudaFuncSetAttribute(gemm_tf32<false>,
                         cudaFuncAttributeMaxDynamicSharedMemorySize, GEMM_SMEM);
    cudaFuncSetAttribute(gemm_tf32<true>,
                         cudaFuncAttributeMaxDynamicSharedMemorySize, GEMM_SMEM);
    cudaFuncSetAttribute(attn_mma,
                         cudaFuncAttributeMaxDynamicSharedMemorySize, ATTN_SMEM);

    // 1) fused = hidden @ qkv_w^T + qkv_b   [2048, 12288]
    gemm_tf32<false><<<dim3(K3 / BN, S_LEN / BM), 256, GEMM_SMEM>>>(
        hidden, qkv_w, qkv_b, nullptr, fused_p, S_LEN, K3, H_DIM);

    // 2) attention -> g_ctx [2048, 4096]
    attn_mma<<<dim3(S_LEN / AQM, NHEADS), 256, ATTN_SMEM>>>(alibi);

    // 3) out = ctx @ dense_w^T + dense_b + residual
    gemm_tf32<true><<<dim3(H_DIM / BN, S_LEN / BM), 256, GEMM_SMEM>>>(
        ctx_p, dense_w, dense_b, resid, out, S_LEN, H_DIM, H_DIM);
}

// round 11
// speedup vs baseline: 1.5681x; 1.0975x over previous
#include <cuda_runtime.h>
#include <stdint.h>
#include <math.h>

// Problem constants
#define S_LEN   2048
#define H_DIM   4096
#define NHEADS  32
#define HD      128
#define K3      12288            // 3*H
#define INV_NORM 0.08838834764831845f   // 1/sqrt(128)

typedef unsigned int u32;

// Scratch (device globals: allocation-free)
__device__ float g_fused[(size_t)S_LEN * K3];   // [S, NH, 3, HD]
__device__ float g_ctx[(size_t)S_LEN * H_DIM];  // [S, H]

// ---------------------------------------------------------------------------
// Common tensor-core helpers (tf32 m16n8k8)
// ---------------------------------------------------------------------------
__device__ __forceinline__ u32 f2tf32(float x) {
    u32 r;
    asm("cvt.rna.tf32.f32 %0, %1;" : "=r"(r) : "f"(x));
    return r;
}

__device__ __forceinline__ void mma_tf32(float c[4], const u32 a[4],
                                         const u32 b[2]) {
    asm volatile(
        "mma.sync.aligned.m16n8k8.row.col.f32.tf32.tf32.f32 "
        "{%0,%1,%2,%3}, {%4,%5,%6,%7}, {%8,%9}, {%0,%1,%2,%3};"
        : "+f"(c[0]), "+f"(c[1]), "+f"(c[2]), "+f"(c[3])
        : "r"(a[0]), "r"(a[1]), "r"(a[2]), "r"(a[3]), "r"(b[0]), "r"(b[1]));
}

__device__ __forceinline__ void cpasync16(float* dst_smem, const float* src) {
    u32 sd = (u32)__cvta_generic_to_shared(dst_smem);
    asm volatile("cp.async.cg.shared.global [%0], [%1], 16;"
                 :: "r"(sd), "l"(src));
}

// ---------------------------------------------------------------------------
// tf32 tensor-core GEMM: C = A @ Bw^T + bias (+resid)
// 128x128x32 tile, 256 threads, warp tile 64x32, cp.async double buffer.
// Paired-k fragment loads (LDS.64): mma slot q4 <- smem col 2*q4,
// slot q4+4 <- smem col 2*q4+1, same permutation for A and B (exact).
// ---------------------------------------------------------------------------
#define BM 128
#define BN 128
#define BK 32
#define SPITCH 40                  // 8*row + 2*q4 -> conflict-free LDS.64
#define TILE_WORDS (BM * SPITCH)   // 5120
#define GEMM_SMEM (4 * TILE_WORDS * 4)   // 81920 B

template<bool ADD_RES>
__global__ __launch_bounds__(256, 2) void gemm_tf32(
    const float* __restrict__ A, const float* __restrict__ Bw,
    const float* __restrict__ bias, const float* __restrict__ resid,
    float* __restrict__ C, int M, int N, int K)
{
    extern __shared__ float sm[];
    float* Abuf[2] = { sm,                  sm + TILE_WORDS };
    float* Bbuf[2] = { sm + 2 * TILE_WORDS, sm + 3 * TILE_WORDS };

    const int tid  = threadIdx.x;
    const int warp = tid >> 5;
    const int lane = tid & 31;
    const int wm   = (warp & 1) * 64;
    const int wn   = (warp >> 1) * 32;
    const int lr   = tid >> 3;
    const int lc   = (tid & 7) * 4;

    const float* Ab = A  + (size_t)blockIdx.y * BM * K;
    const float* Bb = Bw + (size_t)blockIdx.x * BN * K;

    float acc[4][4][4];
#pragma unroll
    for (int i = 0; i < 4; i++)
#pragma unroll
        for (int j = 0; j < 4; j++)
#pragma unroll
            for (int r = 0; r < 4; r++) acc[i][j][r] = 0.f;

#pragma unroll
    for (int i = 0; i < 4; i++) {
        const int row = lr + i * 32;
        cpasync16(&Abuf[0][row * SPITCH + lc], Ab + (size_t)row * K + lc);
        cpasync16(&Bbuf[0][row * SPITCH + lc], Bb + (size_t)row * K + lc);
    }
    asm volatile("cp.async.commit_group;");
    asm volatile("cp.async.wait_group 0;");
    __syncthreads();

    const int NT = K / BK;
    for (int t = 0; t < NT; t++) {
        const int buf = t & 1;
        if (t + 1 < NT) {
            const int nxt = buf ^ 1;
            const int koff = (t + 1) * BK;
#pragma unroll
            for (int i = 0; i < 4; i++) {
                const int row = lr + i * 32;
                cpasync16(&Abuf[nxt][row * SPITCH + lc],
                          Ab + (size_t)row * K + koff + lc);
                cpasync16(&Bbuf[nxt][row * SPITCH + lc],
                          Bb + (size_t)row * K + koff + lc);
            }
        }
        asm volatile("cp.async.commit_group;");

        const float* As = Abuf[buf];
        const float* Bs = Bbuf[buf];

#pragma unroll
        for (int kk = 0; kk < BK; kk += 8) {
            u32 af[4][4], bf[4][2];
            const int kb = kk + 2 * (lane & 3);   // paired-k base
#pragma unroll
            for (int mf = 0; mf < 4; mf++) {
                const int r0 = wm + mf * 16 + (lane >> 2);
                const float2 x0 = *(const float2*)&As[r0 * SPITCH + kb];
                const float2 x1 = *(const float2*)&As[(r0 + 8) * SPITCH + kb];
                af[mf][0] = f2tf32(x0.x);  // slot q4     <- col kb
                af[mf][2] = f2tf32(x0.y);  // slot q4 + 4 <- col kb + 1
                af[mf][1] = f2tf32(x1.x);
                af[mf][3] = f2tf32(x1.y);
            }
#pragma unroll
            for (int nf = 0; nf < 4; nf++) {
                const int c0 = wn + nf * 8 + (lane >> 2);
                const float2 y = *(const float2*)&Bs[c0 * SPITCH + kb];
                bf[nf][0] = f2tf32(y.x);
                bf[nf][1] = f2tf32(y.y);
            }
#pragma unroll
            for (int mf = 0; mf < 4; mf++)
#pragma unroll
                for (int nf = 0; nf < 4; nf++)
                    mma_tf32(acc[mf][nf], af[mf], bf[nf]);
        }

        asm volatile("cp.async.wait_group 0;");
        __syncthreads();
    }

#pragma unroll
    for (int mf = 0; mf < 4; mf++) {
        const int row = blockIdx.y * BM + wm + mf * 16 + (lane >> 2);
#pragma unroll
        for (int nf = 0; nf < 4; nf++) {
            const int col = blockIdx.x * BN + wn + nf * 8 + 2 * (lane & 3);
            const float b0 = bias[col], b1 = bias[col + 1];
            float v0 = acc[mf][nf][0] + b0;
            float v1 = acc[mf][nf][1] + b1;
            float v2 = acc[mf][nf][2] + b0;
            float v3 = acc[mf][nf][3] + b1;
            if (ADD_RES) {
                v0 += resid[(size_t)row * N + col];
                v1 += resid[(size_t)row * N + col + 1];
                v2 += resid[(size_t)(row + 8) * N + col];
                v3 += resid[(size_t)(row + 8) * N + col + 1];
            }
            *(float2*)(C + (size_t)row * N + col)       = make_float2(v0, v1);
            *(float2*)(C + (size_t)(row + 8) * N + col) = make_float2(v2, v3);
        }
    }
}

// ---------------------------------------------------------------------------
// Tensor-core flash attention (tf32 mma, fp32 softmax, causal + alibi)
// CTA: 128 q-rows x 64-kv tiles, 8 warps. Unchanged from R10 (passing).
// ---------------------------------------------------------------------------
#define AQM 128
#define AKT 64
#define QPITCH 132
#define SCP 68
#define NEG_INF -1e30f
#define ATTN_SMEM ((AQM*QPITCH + 2*AKT*QPITCH + AQM*SCP + S_LEN) * 4)  // 178176

__global__ __launch_bounds__(256, 1) void attn_mma(const float* __restrict__ alibi)
{
    extern __shared__ float sm[];
    float* Qs  = sm;
    float* Ks  = Qs + AQM * QPITCH;
    float* Vs  = Ks + AKT * QPITCH;
    float* Sc  = Vs + AKT * QPITCH;
    float* sal = Sc + AQM * SCP;

    const int qt   = (int)gridDim.x - 1 - (int)blockIdx.x;
    const int q0   = qt * AQM;
    const int h    = blockIdx.y;
    const int tid  = threadIdx.x;
    const int w    = tid >> 5;
    const int lane = tid & 31;
    const int g    = lane >> 2;
    const int q4   = lane & 3;

    {
        const float* qbase = g_fused + (size_t)q0 * K3 + h * 384;
#pragma unroll
        for (int i = 0; i < 16; i++) {
            const int idx = tid + i * 256;
            const int r = idx >> 5, c4 = (idx & 31) * 4;
            *(float4*)(Qs + r * QPITCH + c4) =
                *(const float4*)(qbase + (size_t)r * K3 + c4);
        }
        const float* alibi_h = alibi + (size_t)h * S_LEN;
        for (int idx = tid; idx < q0 + AQM; idx += 256)
            sal[idx] = alibi_h[idx];
    }

    const int r0loc = w * 16 + g;
    const int gr0 = q0 + r0loc;
    const int gr1 = gr0 + 8;

    float o[16][4];
#pragma unroll
    for (int nf = 0; nf < 16; nf++)
#pragma unroll
        for (int r = 0; r < 4; r++) o[nf][r] = 0.f;
    float m0 = NEG_INF, m1 = NEG_INF, l0 = 0.f, l1 = 0.f;

    const int nkt = q0 / AKT + 2;
    for (int kt = 0; kt < nkt; kt++) {
        const int kc = kt * AKT;
        {
            const float* kb = g_fused + (size_t)kc * K3 + h * 384 + 128;
#pragma unroll
            for (int i = 0; i < 8; i++) {
                const int idx = tid + i * 256;
                const int r = idx >> 5, c4 = (idx & 31) * 4;
                cpasync16(Ks + r * QPITCH + c4, kb + (size_t)r * K3 + c4);
                cpasync16(Vs + r * QPITCH + c4, kb + (size_t)r * K3 + 128 + c4);
            }
        }
        asm volatile("cp.async.commit_group;");
        asm volatile("cp.async.wait_group 0;");
        __syncthreads();

        float sacc[8][4];
#pragma unroll
        for (int nf = 0; nf < 8; nf++)
#pragma unroll
            for (int r = 0; r < 4; r++) sacc[nf][r] = 0.f;

#pragma unroll
        for (int kk = 0; kk < 16; kk++) {
            const int kq = kk * 8 + q4;
            u32 af[4];
            af[0] = f2tf32(Qs[r0loc * QPITCH + kq]);
            af[1] = f2tf32(Qs[(r0loc + 8) * QPITCH + kq]);
            af[2] = f2tf32(Qs[r0loc * QPITCH + kq + 4]);
            af[3] = f2tf32(Qs[(r0loc + 8) * QPITCH + kq + 4]);
#pragma unroll
            for (int nf = 0; nf < 8; nf++) {
                const int c0 = nf * 8 + g;
                u32 bf[2];
                bf[0] = f2tf32(Ks[c0 * QPITCH + kq]);
                bf[1] = f2tf32(Ks[c0 * QPITCH + kq + 4]);
                mma_tf32(sacc[nf], af, bf);
            }
        }

        float mx0 = NEG_INF, mx1 = NEG_INF;
#pragma unroll
        for (int nf = 0; nf < 8; nf++) {
            const int j0 = kc + nf * 8 + 2 * q4;
            const float a0 = sal[j0], a1 = sal[j0 + 1];
            const float s0 = (j0     <= gr0) ? sacc[nf][0] * INV_NORM + a0 : NEG_INF;
            const float s1 = (j0 + 1 <= gr0) ? sacc[nf][1] * INV_NORM + a1 : NEG_INF;
            const float s2 = (j0     <= gr1) ? sacc[nf][2] * INV_NORM + a0 : NEG_INF;
            const float s3 = (j0 + 1 <= gr1) ? sacc[nf][3] * INV_NORM + a1 : NEG_INF;
            sacc[nf][0] = s0; sacc[nf][1] = s1;
            sacc[nf][2] = s2; sacc[nf][3] = s3;
            mx0 = fmaxf(mx0, fmaxf(s0, s1));
            mx1 = fmaxf(mx1, fmaxf(s2, s3));
        }
        mx0 = fmaxf(mx0, __shfl_xor_sync(0xffffffffu, mx0, 1));
        mx0 = fmaxf(mx0, __shfl_xor_sync(0xffffffffu, mx0, 2));
        mx1 = fmaxf(mx1, __shfl_xor_sync(0xffffffffu, mx1, 1));
        mx1 = fmaxf(mx1, __shfl_xor_sync(0xffffffffu, mx1, 2));

        const float mn0 = fmaxf(m0, mx0), mn1 = fmaxf(m1, mx1);
        const float sc0 = __expf(m0 - mn0), sc1 = __expf(m1 - mn1);
        m0 = mn0; m1 = mn1;

        float ps0 = 0.f, ps1 = 0.f;
#pragma unroll
        for (int nf = 0; nf < 8; nf++) {
            const float p0 = __expf(sacc[nf][0] - mn0);
            const float p1 = __expf(sacc[nf][1] - mn0);
            const float p2 = __expf(sacc[nf][2] - mn1);
            const float p3 = __expf(sacc[nf][3] - mn1);
            ps0 += p0 + p1; ps1 += p2 + p3;
            const int cj = nf * 8 + 2 * q4;
            *(float2*)(Sc + r0loc * SCP + cj)       = make_float2(p0, p1);
            *(float2*)(Sc + (r0loc + 8) * SCP + cj) = make_float2(p2, p3);
        }
        ps0 += __shfl_xor_sync(0xffffffffu, ps0, 1);
        ps0 += __shfl_xor_sync(0xffffffffu, ps0, 2);
        ps1 += __shfl_xor_sync(0xffffffffu, ps1, 1);
        ps1 += __shfl_xor_sync(0xffffffffu, ps1, 2);
        l0 = l0 * sc0 + ps0;
        l1 = l1 * sc1 + ps1;

#pragma unroll
        for (int nf = 0; nf < 16; nf++) {
            o[nf][0] *= sc0; o[nf][1] *= sc0;
            o[nf][2] *= sc1; o[nf][3] *= sc1;
        }
        __syncwarp();

#pragma unroll
        for (int kk = 0; kk < 8; kk++) {
            const int kq = kk * 8 + q4;
            u32 af[4];
            af[0] = f2tf32(Sc[r0loc * SCP + kq]);
            af[1] = f2tf32(Sc[(r0loc + 8) * SCP + kq]);
            af[2] = f2tf32(Sc[r0loc * SCP + kq + 4]);
            af[3] = f2tf32(Sc[(r0loc + 8) * SCP + kq + 4]);
#pragma unroll
            for (int nf = 0; nf < 16; nf++) {
                const int d = nf * 8 + g;
                u32 bf[2];
                bf[0] = f2tf32(Vs[kq * QPITCH + d]);
                bf[1] = f2tf32(Vs[(kq + 4) * QPITCH + d]);
                mma_tf32(o[nf], af, bf);
            }
        }
        __syncthreads();
    }

    const float inv0 = 1.f / l0, inv1 = 1.f / l1;
    float* dst0 = g_ctx + (size_t)gr0 * H_DIM + h * HD;
    float* dst1 = g_ctx + (size_t)gr1 * H_DIM + h * HD;
#pragma unroll
    for (int nf = 0; nf < 16; nf++) {
        const int d = nf * 8 + 2 * q4;
        *(float2*)(dst0 + d) = make_float2(o[nf][0] * inv0, o[nf][1] * inv0);
        *(float2*)(dst1 + d) = make_float2(o[nf][2] * inv1, o[nf][3] * inv1);
    }
}

// ---------------------------------------------------------------------------
extern "C" void kernel_launch(void* const* d_in, const int* in_sizes, int n_in,
                              void* d_out, int out_size)
{
    const float* hidden  = (const float*)d_in[0];
    const float* resid   = (const float*)d_in[1];
    const float* alibi   = (const float*)d_in[2];
    const float* qkv_w   = (const float*)d_in[4];
    const float* qkv_b   = (const float*)d_in[5];
    const float* dense_w = (const float*)d_in[6];
    const float* dense_b = (const float*)d_in[7];
    float* out = (float*)d_out;

    float *fused_p, *ctx_p;
    cudaGetSymbolAddress((void**)&fused_p, g_fused);
    cudaGetSymbolAddress((void**)&ctx_p, g_ctx);

    cudaFuncSetAttribute(gemm_tf32<false>,
                         cudaFuncAttributeMaxDynamicSharedMemorySize, GEMM_SMEM);
    cudaFuncSetAttribute(gemm_tf32<true>,
                         cudaFuncAttributeMaxDynamicSharedMemorySize, GEMM_SMEM);
    cudaFuncSetAttribute(attn_mma,
                         cudaFuncAttributeMaxDynamicSharedMemorySize, ATTN_SMEM);

    // 1) fused = hidden @ qkv_w^T + qkv_b   [2048, 12288]
    gemm_tf32<false><<<dim3(K3 / BN, S_LEN / BM), 256, GEMM_SMEM>>>(
        hidden, qkv_w, qkv_b, nullptr, fused_p, S_LEN, K3, H_DIM);

    // 2) attention -> g_ctx [2048, 4096]
    attn_mma<<<dim3(S_LEN / AQM, NHEADS), 256, ATTN_SMEM>>>(alibi);

    // 3) out = ctx @ dense_w^T + dense_b + residual
    gemm_tf32<true><<<dim3(H_DIM / BN, S_LEN / BM), 256, GEMM_SMEM>>>(
        ctx_p, dense_w, dense_b, resid, out, S_LEN, H_DIM, H_DIM);
}

// round 12
// speedup vs baseline: 1.6938x; 1.0802x over previous
#include <cuda_runtime.h>
#include <stdint.h>
#include <math.h>

// Problem constants
#define S_LEN   2048
#define H_DIM   4096
#define NHEADS  32
#define HD      128
#define K3      12288            // 3*H
#define INV_NORM 0.08838834764831845f   // 1/sqrt(128)

typedef unsigned int u32;

// Scratch (device globals: allocation-free)
__device__ float g_fused[(size_t)S_LEN * K3];     // [S, NH, 3, HD] tf32-valued
__device__ float g_ctx[(size_t)S_LEN * H_DIM];    // [S, H]        tf32-valued
__device__ float g_hid_t[(size_t)S_LEN * H_DIM];  // tf32 copy of hidden
__device__ float g_qkvw_t[(size_t)K3 * H_DIM];    // tf32 copy of qkv_w
__device__ float g_densew_t[(size_t)H_DIM * H_DIM]; // tf32 copy of dense_w

// ---------------------------------------------------------------------------
// Helpers
// ---------------------------------------------------------------------------
__device__ __forceinline__ u32 f2tf32(float x) {
    u32 r;
    asm("cvt.rna.tf32.f32 %0, %1;" : "=r"(r) : "f"(x));
    return r;
}

__device__ __forceinline__ void mma_tf32(float c[4], const u32 a[4],
                                         const u32 b[2]) {
    asm volatile(
        "mma.sync.aligned.m16n8k8.row.col.f32.tf32.tf32.f32 "
        "{%0,%1,%2,%3}, {%4,%5,%6,%7}, {%8,%9}, {%0,%1,%2,%3};"
        : "+f"(c[0]), "+f"(c[1]), "+f"(c[2]), "+f"(c[3])
        : "r"(a[0]), "r"(a[1]), "r"(a[2]), "r"(a[3]), "r"(b[0]), "r"(b[1]));
}

__device__ __forceinline__ void cpasync16(float* dst_smem, const float* src) {
    u32 sd = (u32)__cvta_generic_to_shared(dst_smem);
    asm volatile("cp.async.cg.shared.global [%0], [%1], 16;"
                 :: "r"(sd), "l"(src));
}

// Elementwise fp32 -> tf32-valued fp32
__global__ __launch_bounds__(256) void cvt_tf32_kernel(
    const float4* __restrict__ src, float4* __restrict__ dst, int n4)
{
    const int i = blockIdx.x * blockDim.x + threadIdx.x;
    if (i < n4) {
        float4 v = src[i];
        float4 o;
        o.x = __uint_as_float(f2tf32(v.x));
        o.y = __uint_as_float(f2tf32(v.y));
        o.z = __uint_as_float(f2tf32(v.z));
        o.w = __uint_as_float(f2tf32(v.w));
        dst[i] = o;
    }
}

// ---------------------------------------------------------------------------
// tf32 tensor-core GEMM: C = A @ Bw^T + bias (+resid). A/Bw are PRE-CONVERTED
// tf32-valued fp32 -> mainloop is pure LDS.64 + HMMA (no cvt).
// 128x128x32 tile, 256 threads, warp tile 64x32, cp.async double buffer.
// Paired-k: mma slot q4 <- col 2*q4, slot q4+4 <- col 2*q4+1 (A and B alike).
// CVT_OUT: store tf32-rounded outputs (for tensors consumed by later mma).
// ---------------------------------------------------------------------------
#define BM 128
#define BN 128
#define BK 32
#define SPITCH 40
#define TILE_WORDS (BM * SPITCH)
#define GEMM_SMEM (4 * TILE_WORDS * 4)   // 81920 B

template<bool ADD_RES, bool CVT_OUT>
__global__ __launch_bounds__(256, 2) void gemm_tf32(
    const float* __restrict__ A, const float* __restrict__ Bw,
    const float* __restrict__ bias, const float* __restrict__ resid,
    float* __restrict__ C, int M, int N, int K)
{
    extern __shared__ float sm[];
    float* Abuf[2] = { sm,                  sm + TILE_WORDS };
    float* Bbuf[2] = { sm + 2 * TILE_WORDS, sm + 3 * TILE_WORDS };

    const int tid  = threadIdx.x;
    const int warp = tid >> 5;
    const int lane = tid & 31;
    const int wm   = (warp & 1) * 64;
    const int wn   = (warp >> 1) * 32;
    const int lr   = tid >> 3;
    const int lc   = (tid & 7) * 4;

    const float* Ab = A  + (size_t)blockIdx.y * BM * K;
    const float* Bb = Bw + (size_t)blockIdx.x * BN * K;

    float acc[4][4][4];
#pragma unroll
    for (int i = 0; i < 4; i++)
#pragma unroll
        for (int j = 0; j < 4; j++)
#pragma unroll
            for (int r = 0; r < 4; r++) acc[i][j][r] = 0.f;

#pragma unroll
    for (int i = 0; i < 4; i++) {
        const int row = lr + i * 32;
        cpasync16(&Abuf[0][row * SPITCH + lc], Ab + (size_t)row * K + lc);
        cpasync16(&Bbuf[0][row * SPITCH + lc], Bb + (size_t)row * K + lc);
    }
    asm volatile("cp.async.commit_group;");
    asm volatile("cp.async.wait_group 0;");
    __syncthreads();

    const int NT = K / BK;
    for (int t = 0; t < NT; t++) {
        const int buf = t & 1;
        if (t + 1 < NT) {
            const int nxt = buf ^ 1;
            const int koff = (t + 1) * BK;
#pragma unroll
            for (int i = 0; i < 4; i++) {
                const int row = lr + i * 32;
                cpasync16(&Abuf[nxt][row * SPITCH + lc],
                          Ab + (size_t)row * K + koff + lc);
                cpasync16(&Bbuf[nxt][row * SPITCH + lc],
                          Bb + (size_t)row * K + koff + lc);
            }
        }
        asm volatile("cp.async.commit_group;");

        const float* As = Abuf[buf];
        const float* Bs = Bbuf[buf];

#pragma unroll
        for (int kk = 0; kk < BK; kk += 8) {
            u32 af[4][4], bf[4][2];
            const int kb = kk + 2 * (lane & 3);
#pragma unroll
            for (int mf = 0; mf < 4; mf++) {
                const int r0 = wm + mf * 16 + (lane >> 2);
                const uint2 x0 = *(const uint2*)&As[r0 * SPITCH + kb];
                const uint2 x1 = *(const uint2*)&As[(r0 + 8) * SPITCH + kb];
                af[mf][0] = x0.x; af[mf][2] = x0.y;
                af[mf][1] = x1.x; af[mf][3] = x1.y;
            }
#pragma unroll
            for (int nf = 0; nf < 4; nf++) {
                const int c0 = wn + nf * 8 + (lane >> 2);
                const uint2 y = *(const uint2*)&Bs[c0 * SPITCH + kb];
                bf[nf][0] = y.x; bf[nf][1] = y.y;
            }
#pragma unroll
            for (int mf = 0; mf < 4; mf++)
#pragma unroll
                for (int nf = 0; nf < 4; nf++)
                    mma_tf32(acc[mf][nf], af[mf], bf[nf]);
        }

        asm volatile("cp.async.wait_group 0;");
        __syncthreads();
    }

#pragma unroll
    for (int mf = 0; mf < 4; mf++) {
        const int row = blockIdx.y * BM + wm + mf * 16 + (lane >> 2);
#pragma unroll
        for (int nf = 0; nf < 4; nf++) {
            const int col = blockIdx.x * BN + wn + nf * 8 + 2 * (lane & 3);
            const float b0 = bias[col], b1 = bias[col + 1];
            float v0 = acc[mf][nf][0] + b0;
            float v1 = acc[mf][nf][1] + b1;
            float v2 = acc[mf][nf][2] + b0;
            float v3 = acc[mf][nf][3] + b1;
            if (ADD_RES) {
                v0 += resid[(size_t)row * N + col];
                v1 += resid[(size_t)row * N + col + 1];
                v2 += resid[(size_t)(row + 8) * N + col];
                v3 += resid[(size_t)(row + 8) * N + col + 1];
            }
            if (CVT_OUT) {
                v0 = __uint_as_float(f2tf32(v0));
                v1 = __uint_as_float(f2tf32(v1));
                v2 = __uint_as_float(f2tf32(v2));
                v3 = __uint_as_float(f2tf32(v3));
            }
            *(float2*)(C + (size_t)row * N + col)       = make_float2(v0, v1);
            *(float2*)(C + (size_t)(row + 8) * N + col) = make_float2(v2, v3);
        }
    }
}

// ---------------------------------------------------------------------------
// Tensor-core flash attention. Q/K/V in g_fused are tf32-valued already:
// no cvt on Q/K/V reads; paired-k LDS.64 on Q, K, P. fp32 softmax.
// ---------------------------------------------------------------------------
#define AQM 128
#define AKT 64
#define QPITCH 132
#define SCP 68
#define NEG_INF -1e30f
#define ATTN_SMEM ((AQM*QPITCH + 2*AKT*QPITCH + AQM*SCP + S_LEN) * 4)  // 178176

__global__ __launch_bounds__(256, 1) void attn_mma(const float* __restrict__ alibi)
{
    extern __shared__ float sm[];
    float* Qs  = sm;
    float* Ks  = Qs + AQM * QPITCH;
    float* Vs  = Ks + AKT * QPITCH;
    float* Sc  = Vs + AKT * QPITCH;
    float* sal = Sc + AQM * SCP;

    const int qt   = (int)gridDim.x - 1 - (int)blockIdx.x;
    const int q0   = qt * AQM;
    const int h    = blockIdx.y;
    const int tid  = threadIdx.x;
    const int w    = tid >> 5;
    const int lane = tid & 31;
    const int g    = lane >> 2;
    const int q4   = lane & 3;

    {
        const float* qbase = g_fused + (size_t)q0 * K3 + h * 384;
#pragma unroll
        for (int i = 0; i < 16; i++) {
            const int idx = tid + i * 256;
            const int r = idx >> 5, c4 = (idx & 31) * 4;
            *(float4*)(Qs + r * QPITCH + c4) =
                *(const float4*)(qbase + (size_t)r * K3 + c4);
        }
        const float* alibi_h = alibi + (size_t)h * S_LEN;
        for (int idx = tid; idx < q0 + AQM; idx += 256)
            sal[idx] = alibi_h[idx];
    }

    const int r0loc = w * 16 + g;
    const int gr0 = q0 + r0loc;
    const int gr1 = gr0 + 8;

    float o[16][4];
#pragma unroll
    for (int nf = 0; nf < 16; nf++)
#pragma unroll
        for (int r = 0; r < 4; r++) o[nf][r] = 0.f;
    float m0 = NEG_INF, m1 = NEG_INF, l0 = 0.f, l1 = 0.f;

    const int nkt = q0 / AKT + 2;
    for (int kt = 0; kt < nkt; kt++) {
        const int kc = kt * AKT;
        {
            const float* kb = g_fused + (size_t)kc * K3 + h * 384 + 128;
#pragma unroll
            for (int i = 0; i < 8; i++) {
                const int idx = tid + i * 256;
                const int r = idx >> 5, c4 = (idx & 31) * 4;
                cpasync16(Ks + r * QPITCH + c4, kb + (size_t)r * K3 + c4);
                cpasync16(Vs + r * QPITCH + c4, kb + (size_t)r * K3 + 128 + c4);
            }
        }
        asm volatile("cp.async.commit_group;");
        asm volatile("cp.async.wait_group 0;");
        __syncthreads();

        // S = Q K^T (paired-k, pre-converted operands)
        float sacc[8][4];
#pragma unroll
        for (int nf = 0; nf < 8; nf++)
#pragma unroll
            for (int r = 0; r < 4; r++) sacc[nf][r] = 0.f;

#pragma unroll
        for (int kk = 0; kk < 16; kk++) {
            const int kb = kk * 8 + 2 * q4;
            u32 af[4];
            const uint2 a0 = *(const uint2*)&Qs[r0loc * QPITCH + kb];
            const uint2 a1 = *(const uint2*)&Qs[(r0loc + 8) * QPITCH + kb];
            af[0] = a0.x; af[2] = a0.y;
            af[1] = a1.x; af[3] = a1.y;
#pragma unroll
            for (int nf = 0; nf < 8; nf++) {
                const int c0 = nf * 8 + g;
                const uint2 b0 = *(const uint2*)&Ks[c0 * QPITCH + kb];
                u32 bf[2];
                bf[0] = b0.x; bf[1] = b0.y;
                mma_tf32(sacc[nf], af, bf);
            }
        }

        float mx0 = NEG_INF, mx1 = NEG_INF;
#pragma unroll
        for (int nf = 0; nf < 8; nf++) {
            const int j0 = kc + nf * 8 + 2 * q4;
            const float a0 = sal[j0], a1 = sal[j0 + 1];
            const float s0 = (j0     <= gr0) ? sacc[nf][0] * INV_NORM + a0 : NEG_INF;
            const float s1 = (j0 + 1 <= gr0) ? sacc[nf][1] * INV_NORM + a1 : NEG_INF;
            const float s2 = (j0     <= gr1) ? sacc[nf][2] * INV_NORM + a0 : NEG_INF;
            const float s3 = (j0 + 1 <= gr1) ? sacc[nf][3] * INV_NORM + a1 : NEG_INF;
            sacc[nf][0] = s0; sacc[nf][1] = s1;
            sacc[nf][2] = s2; sacc[nf][3] = s3;
            mx0 = fmaxf(mx0, fmaxf(s0, s1));
            mx1 = fmaxf(mx1, fmaxf(s2, s3));
        }
        mx0 = fmaxf(mx0, __shfl_xor_sync(0xffffffffu, mx0, 1));
        mx0 = fmaxf(mx0, __shfl_xor_sync(0xffffffffu, mx0, 2));
        mx1 = fmaxf(mx1, __shfl_xor_sync(0xffffffffu, mx1, 1));
        mx1 = fmaxf(mx1, __shfl_xor_sync(0xffffffffu, mx1, 2));

        const float mn0 = fmaxf(m0, mx0), mn1 = fmaxf(m1, mx1);
        const float sc0 = __expf(m0 - mn0), sc1 = __expf(m1 - mn1);
        m0 = mn0; m1 = mn1;

        float ps0 = 0.f, ps1 = 0.f;
#pragma unroll
        for (int nf = 0; nf < 8; nf++) {
            const float p0 = __expf(sacc[nf][0] - mn0);
            const float p1 = __expf(sacc[nf][1] - mn0);
            const float p2 = __expf(sacc[nf][2] - mn1);
            const float p3 = __expf(sacc[nf][3] - mn1);
            ps0 += p0 + p1; ps1 += p2 + p3;
            const int cj = nf * 8 + 2 * q4;
            *(float2*)(Sc + r0loc * SCP + cj)       = make_float2(p0, p1);
            *(float2*)(Sc + (r0loc + 8) * SCP + cj) = make_float2(p2, p3);
        }
        ps0 += __shfl_xor_sync(0xffffffffu, ps0, 1);
        ps0 += __shfl_xor_sync(0xffffffffu, ps0, 2);
        ps1 += __shfl_xor_sync(0xffffffffu, ps1, 1);
        ps1 += __shfl_xor_sync(0xffffffffu, ps1, 2);
        l0 = l0 * sc0 + ps0;
        l1 = l1 * sc1 + ps1;

#pragma unroll
        for (int nf = 0; nf < 16; nf++) {
            o[nf][0] *= sc0; o[nf][1] *= sc0;
            o[nf][2] *= sc1; o[nf][3] *= sc1;
        }
        __syncwarp();

        // O += P V (paired-k rows of V; P cvt at load, V pre-converted)
#pragma unroll
        for (int kk = 0; kk < 8; kk++) {
            const int kb = kk * 8 + 2 * q4;
            u32 af[4];
            const float2 p0 = *(const float2*)&Sc[r0loc * SCP + kb];
            const float2 p1 = *(const float2*)&Sc[(r0loc + 8) * SCP + kb];
            af[0] = f2tf32(p0.x); af[2] = f2tf32(p0.y);
            af[1] = f2tf32(p1.x); af[3] = f2tf32(p1.y);
#pragma unroll
            for (int nf = 0; nf < 16; nf++) {
                const int d = nf * 8 + g;
                u32 bf[2];
                bf[0] = __float_as_uint(Vs[kb * QPITCH + d]);
                bf[1] = __float_as_uint(Vs[(kb + 1) * QPITCH + d]);
                mma_tf32(o[nf], af, bf);
            }
        }
        __syncthreads();
    }

    // Normalize + write ctx as tf32-valued fp32 (dense GEMM consumes via mma)
    const float inv0 = 1.f / l0, inv1 = 1.f / l1;
    float* dst0 = g_ctx + (size_t)gr0 * H_DIM + h * HD;
    float* dst1 = g_ctx + (size_t)gr1 * H_DIM + h * HD;
#pragma unroll
    for (int nf = 0; nf < 16; nf++) {
        const int d = nf * 8 + 2 * q4;
        float2 w0 = make_float2(__uint_as_float(f2tf32(o[nf][0] * inv0)),
                                __uint_as_float(f2tf32(o[nf][1] * inv0)));
        float2 w1 = make_float2(__uint_as_float(f2tf32(o[nf][2] * inv1)),
                                __uint_as_float(f2tf32(o[nf][3] * inv1)));
        *(float2*)(dst0 + d) = w0;
        *(float2*)(dst1 + d) = w1;
    }
}

// ---------------------------------------------------------------------------
extern "C" void kernel_launch(void* const* d_in, const int* in_sizes, int n_in,
                              void* d_out, int out_size)
{
    const float* hidden  = (const float*)d_in[0];
    const float* resid   = (const float*)d_in[1];
    const float* alibi   = (const float*)d_in[2];
    const float* qkv_w   = (const float*)d_in[4];
    const float* qkv_b   = (const float*)d_in[5];
    const float* dense_w = (const float*)d_in[6];
    const float* dense_b = (const float*)d_in[7];
    float* out = (float*)d_out;

    float *fused_p, *ctx_p, *hid_t, *qkvw_t, *densew_t;
    cudaGetSymbolAddress((void**)&fused_p, g_fused);
    cudaGetSymbolAddress((void**)&ctx_p, g_ctx);
    cudaGetSymbolAddress((void**)&hid_t, g_hid_t);
    cudaGetSymbolAddress((void**)&qkvw_t, g_qkvw_t);
    cudaGetSymbolAddress((void**)&densew_t, g_densew_t);

    cudaFuncSetAttribute(gemm_tf32<false, true>,
                         cudaFuncAttributeMaxDynamicSharedMemorySize, GEMM_SMEM);
    cudaFuncSetAttribute(gemm_tf32<true, false>,
                         cudaFuncAttributeMaxDynamicSharedMemorySize, GEMM_SMEM);
    cudaFuncSetAttribute(attn_mma,
                         cudaFuncAttributeMaxDynamicSharedMemorySize, ATTN_SMEM);

    // 0) Pre-convert inputs/weights to tf32-valued fp32
    {
        const int n4h = (S_LEN * H_DIM) / 4;
        cvt_tf32_kernel<<<(n4h + 255) / 256, 256>>>(
            (const float4*)hidden, (float4*)hid_t, n4h);
        const int n4q = (K3 * H_DIM) / 4;
        cvt_tf32_kernel<<<(n4q + 255) / 256, 256>>>(
            (const float4*)qkv_w, (float4*)qkvw_t, n4q);
        const int n4d = (H_DIM * H_DIM) / 4;
        cvt_tf32_kernel<<<(n4d + 255) / 256, 256>>>(
            (const float4*)dense_w, (float4*)densew_t, n4d);
    }

    // 1) fused = hidden @ qkv_w^T + qkv_b (tf32-rounded out)
    gemm_tf32<false, true><<<dim3(K3 / BN, S_LEN / BM), 256, GEMM_SMEM>>>(
        hid_t, qkvw_t, qkv_b, nullptr, fused_p, S_LEN, K3, H_DIM);

    // 2) attention -> g_ctx (tf32-rounded out)
    attn_mma<<<dim3(S_LEN / AQM, NHEADS), 256, ATTN_SMEM>>>(alibi);

    // 3) out = ctx @ dense_w^T + dense_b + residual (fp32 out)
    gemm_tf32<true, false><<<dim3(H_DIM / BN, S_LEN / BM), 256, GEMM_SMEM>>>(
        ctx_p, densew_t, dense_b, resid, out, S_LEN, H_DIM, H_DIM);
}

// round 13
// speedup vs baseline: 1.7146x; 1.0122x over previous
#include <cuda_runtime.h>
#include <stdint.h>
#include <math.h>

// Problem constants
#define S_LEN   2048
#define H_DIM   4096
#define NHEADS  32
#define HD      128
#define K3      12288            // 3*H
#define INV_NORM 0.08838834764831845f   // 1/sqrt(128)

typedef unsigned int u32;

// Scratch (device globals: allocation-free)
__device__ float g_fused[(size_t)S_LEN * K3];     // [S, NH, 3, HD] tf32-valued
__device__ float g_ctx[(size_t)S_LEN * H_DIM];    // [S, H]        tf32-valued
__device__ float g_hid_t[(size_t)S_LEN * H_DIM];  // tf32 copy of hidden
__device__ float g_qkvw_t[(size_t)K3 * H_DIM];    // tf32 copy of qkv_w
__device__ float g_densew_t[(size_t)H_DIM * H_DIM]; // tf32 copy of dense_w

// ---------------------------------------------------------------------------
// Helpers
// ---------------------------------------------------------------------------
__device__ __forceinline__ u32 f2tf32(float x) {
    u32 r;
    asm("cvt.rna.tf32.f32 %0, %1;" : "=r"(r) : "f"(x));
    return r;
}

__device__ __forceinline__ void mma_tf32(float c[4], const u32 a[4],
                                         const u32 b[2]) {
    asm volatile(
        "mma.sync.aligned.m16n8k8.row.col.f32.tf32.tf32.f32 "
        "{%0,%1,%2,%3}, {%4,%5,%6,%7}, {%8,%9}, {%0,%1,%2,%3};"
        : "+f"(c[0]), "+f"(c[1]), "+f"(c[2]), "+f"(c[3])
        : "r"(a[0]), "r"(a[1]), "r"(a[2]), "r"(a[3]), "r"(b[0]), "r"(b[1]));
}

__device__ __forceinline__ void cpasync16(float* dst_smem, const float* src) {
    u32 sd = (u32)__cvta_generic_to_shared(dst_smem);
    asm volatile("cp.async.cg.shared.global [%0], [%1], 16;"
                 :: "r"(sd), "l"(src));
}

// Elementwise fp32 -> tf32-valued fp32
__global__ __launch_bounds__(256) void cvt_tf32_kernel(
    const float4* __restrict__ src, float4* __restrict__ dst, int n4)
{
    const int i = blockIdx.x * blockDim.x + threadIdx.x;
    if (i < n4) {
        float4 v = src[i];
        float4 o;
        o.x = __uint_as_float(f2tf32(v.x));
        o.y = __uint_as_float(f2tf32(v.y));
        o.z = __uint_as_float(f2tf32(v.z));
        o.w = __uint_as_float(f2tf32(v.w));
        dst[i] = o;
    }
}

// ---------------------------------------------------------------------------
// tf32 tensor-core GEMM: C = A @ Bw^T + bias (+resid). A/Bw PRE-CONVERTED.
// 128x128x32 tile, 256 threads, warp tile 64x32, cp.async double buffer.
// GRID: blockIdx.x = M-tile (fast) so one wave reuses few B tiles from L2.
// ---------------------------------------------------------------------------
#define BM 128
#define BN 128
#define BK 32
#define SPITCH 40
#define TILE_WORDS (BM * SPITCH)
#define GEMM_SMEM (4 * TILE_WORDS * 4)   // 81920 B

template<bool ADD_RES, bool CVT_OUT>
__global__ __launch_bounds__(256, 2) void gemm_tf32(
    const float* __restrict__ A, const float* __restrict__ Bw,
    const float* __restrict__ bias, const float* __restrict__ resid,
    float* __restrict__ C, int M, int N, int K)
{
    extern __shared__ float sm[];
    float* Abuf[2] = { sm,                  sm + TILE_WORDS };
    float* Bbuf[2] = { sm + 2 * TILE_WORDS, sm + 3 * TILE_WORDS };

    const int tid  = threadIdx.x;
    const int warp = tid >> 5;
    const int lane = tid & 31;
    const int wm   = (warp & 1) * 64;
    const int wn   = (warp >> 1) * 32;
    const int lr   = tid >> 3;
    const int lc   = (tid & 7) * 4;

    // M-tile on x (fast dim), N-tile on y (slow) -> B tiles L2-resident
    const int mt = blockIdx.x;
    const int nt = blockIdx.y;

    const float* Ab = A  + (size_t)mt * BM * K;
    const float* Bb = Bw + (size_t)nt * BN * K;

    float acc[4][4][4];
#pragma unroll
    for (int i = 0; i < 4; i++)
#pragma unroll
        for (int j = 0; j < 4; j++)
#pragma unroll
            for (int r = 0; r < 4; r++) acc[i][j][r] = 0.f;

#pragma unroll
    for (int i = 0; i < 4; i++) {
        const int row = lr + i * 32;
        cpasync16(&Abuf[0][row * SPITCH + lc], Ab + (size_t)row * K + lc);
        cpasync16(&Bbuf[0][row * SPITCH + lc], Bb + (size_t)row * K + lc);
    }
    asm volatile("cp.async.commit_group;");
    asm volatile("cp.async.wait_group 0;");
    __syncthreads();

    const int NT = K / BK;
    for (int t = 0; t < NT; t++) {
        const int buf = t & 1;
        if (t + 1 < NT) {
            const int nxt = buf ^ 1;
            const int koff = (t + 1) * BK;
#pragma unroll
            for (int i = 0; i < 4; i++) {
                const int row = lr + i * 32;
                cpasync16(&Abuf[nxt][row * SPITCH + lc],
                          Ab + (size_t)row * K + koff + lc);
                cpasync16(&Bbuf[nxt][row * SPITCH + lc],
                          Bb + (size_t)row * K + koff + lc);
            }
        }
        asm volatile("cp.async.commit_group;");

        const float* As = Abuf[buf];
        const float* Bs = Bbuf[buf];

#pragma unroll
        for (int kk = 0; kk < BK; kk += 8) {
            u32 af[4][4], bf[4][2];
            const int kb = kk + 2 * (lane & 3);
#pragma unroll
            for (int mf = 0; mf < 4; mf++) {
                const int r0 = wm + mf * 16 + (lane >> 2);
                const uint2 x0 = *(const uint2*)&As[r0 * SPITCH + kb];
                const uint2 x1 = *(const uint2*)&As[(r0 + 8) * SPITCH + kb];
                af[mf][0] = x0.x; af[mf][2] = x0.y;
                af[mf][1] = x1.x; af[mf][3] = x1.y;
            }
#pragma unroll
            for (int nf = 0; nf < 4; nf++) {
                const int c0 = wn + nf * 8 + (lane >> 2);
                const uint2 y = *(const uint2*)&Bs[c0 * SPITCH + kb];
                bf[nf][0] = y.x; bf[nf][1] = y.y;
            }
#pragma unroll
            for (int mf = 0; mf < 4; mf++)
#pragma unroll
                for (int nf = 0; nf < 4; nf++)
                    mma_tf32(acc[mf][nf], af[mf], bf[nf]);
        }

        asm volatile("cp.async.wait_group 0;");
        __syncthreads();
    }

#pragma unroll
    for (int mf = 0; mf < 4; mf++) {
        const int row = mt * BM + wm + mf * 16 + (lane >> 2);
#pragma unroll
        for (int nf = 0; nf < 4; nf++) {
            const int col = nt * BN + wn + nf * 8 + 2 * (lane & 3);
            const float b0 = bias[col], b1 = bias[col + 1];
            float v0 = acc[mf][nf][0] + b0;
            float v1 = acc[mf][nf][1] + b1;
            float v2 = acc[mf][nf][2] + b0;
            float v3 = acc[mf][nf][3] + b1;
            if (ADD_RES) {
                v0 += resid[(size_t)row * N + col];
                v1 += resid[(size_t)row * N + col + 1];
                v2 += resid[(size_t)(row + 8) * N + col];
                v3 += resid[(size_t)(row + 8) * N + col + 1];
            }
            if (CVT_OUT) {
                v0 = __uint_as_float(f2tf32(v0));
                v1 = __uint_as_float(f2tf32(v1));
                v2 = __uint_as_float(f2tf32(v2));
                v3 = __uint_as_float(f2tf32(v3));
            }
            *(float2*)(C + (size_t)row * N + col)       = make_float2(v0, v1);
            *(float2*)(C + (size_t)(row + 8) * N + col) = make_float2(v2, v3);
        }
    }
}

// ---------------------------------------------------------------------------
// Tensor-core flash attention (unchanged from R12, passing).
// ---------------------------------------------------------------------------
#define AQM 128
#define AKT 64
#define QPITCH 132
#define SCP 68
#define NEG_INF -1e30f
#define ATTN_SMEM ((AQM*QPITCH + 2*AKT*QPITCH + AQM*SCP + S_LEN) * 4)  // 178176

__global__ __launch_bounds__(256, 1) void attn_mma(const float* __restrict__ alibi)
{
    extern __shared__ float sm[];
    float* Qs  = sm;
    float* Ks  = Qs + AQM * QPITCH;
    float* Vs  = Ks + AKT * QPITCH;
    float* Sc  = Vs + AKT * QPITCH;
    float* sal = Sc + AQM * SCP;

    const int qt   = (int)gridDim.x - 1 - (int)blockIdx.x;
    const int q0   = qt * AQM;
    const int h    = blockIdx.y;
    const int tid  = threadIdx.x;
    const int w    = tid >> 5;
    const int lane = tid & 31;
    const int g    = lane >> 2;
    const int q4   = lane & 3;

    {
        const float* qbase = g_fused + (size_t)q0 * K3 + h * 384;
#pragma unroll
        for (int i = 0; i < 16; i++) {
            const int idx = tid + i * 256;
            const int r = idx >> 5, c4 = (idx & 31) * 4;
            *(float4*)(Qs + r * QPITCH + c4) =
                *(const float4*)(qbase + (size_t)r * K3 + c4);
        }
        const float* alibi_h = alibi + (size_t)h * S_LEN;
        for (int idx = tid; idx < q0 + AQM; idx += 256)
            sal[idx] = alibi_h[idx];
    }

    const int r0loc = w * 16 + g;
    const int gr0 = q0 + r0loc;
    const int gr1 = gr0 + 8;

    float o[16][4];
#pragma unroll
    for (int nf = 0; nf < 16; nf++)
#pragma unroll
        for (int r = 0; r < 4; r++) o[nf][r] = 0.f;
    float m0 = NEG_INF, m1 = NEG_INF, l0 = 0.f, l1 = 0.f;

    const int nkt = q0 / AKT + 2;
    for (int kt = 0; kt < nkt; kt++) {
        const int kc = kt * AKT;
        {
            const float* kb = g_fused + (size_t)kc * K3 + h * 384 + 128;
#pragma unroll
            for (int i = 0; i < 8; i++) {
                const int idx = tid + i * 256;
                const int r = idx >> 5, c4 = (idx & 31) * 4;
                cpasync16(Ks + r * QPITCH + c4, kb + (size_t)r * K3 + c4);
                cpasync16(Vs + r * QPITCH + c4, kb + (size_t)r * K3 + 128 + c4);
            }
        }
        asm volatile("cp.async.commit_group;");
        asm volatile("cp.async.wait_group 0;");
        __syncthreads();

        float sacc[8][4];
#pragma unroll
        for (int nf = 0; nf < 8; nf++)
#pragma unroll
            for (int r = 0; r < 4; r++) sacc[nf][r] = 0.f;

#pragma unroll
        for (int kk = 0; kk < 16; kk++) {
            const int kb = kk * 8 + 2 * q4;
            u32 af[4];
            const uint2 a0 = *(const uint2*)&Qs[r0loc * QPITCH + kb];
            const uint2 a1 = *(const uint2*)&Qs[(r0loc + 8) * QPITCH + kb];
            af[0] = a0.x; af[2] = a0.y;
            af[1] = a1.x; af[3] = a1.y;
#pragma unroll
            for (int nf = 0; nf < 8; nf++) {
                const int c0 = nf * 8 + g;
                const uint2 b0 = *(const uint2*)&Ks[c0 * QPITCH + kb];
                u32 bf[2];
                bf[0] = b0.x; bf[1] = b0.y;
                mma_tf32(sacc[nf], af, bf);
            }
        }

        float mx0 = NEG_INF, mx1 = NEG_INF;
#pragma unroll
        for (int nf = 0; nf < 8; nf++) {
            const int j0 = kc + nf * 8 + 2 * q4;
            const float a0 = sal[j0], a1 = sal[j0 + 1];
            const float s0 = (j0     <= gr0) ? sacc[nf][0] * INV_NORM + a0 : NEG_INF;
            const float s1 = (j0 + 1 <= gr0) ? sacc[nf][1] * INV_NORM + a1 : NEG_INF;
            const float s2 = (j0     <= gr1) ? sacc[nf][2] * INV_NORM + a0 : NEG_INF;
            const float s3 = (j0 + 1 <= gr1) ? sacc[nf][3] * INV_NORM + a1 : NEG_INF;
            sacc[nf][0] = s0; sacc[nf][1] = s1;
            sacc[nf][2] = s2; sacc[nf][3] = s3;
            mx0 = fmaxf(mx0, fmaxf(s0, s1));
            mx1 = fmaxf(mx1, fmaxf(s2, s3));
        }
        mx0 = fmaxf(mx0, __shfl_xor_sync(0xffffffffu, mx0, 1));
        mx0 = fmaxf(mx0, __shfl_xor_sync(0xffffffffu, mx0, 2));
        mx1 = fmaxf(mx1, __shfl_xor_sync(0xffffffffu, mx1, 1));
        mx1 = fmaxf(mx1, __shfl_xor_sync(0xffffffffu, mx1, 2));

        const float mn0 = fmaxf(m0, mx0), mn1 = fmaxf(m1, mx1);
        const float sc0 = __expf(m0 - mn0), sc1 = __expf(m1 - mn1);
        m0 = mn0; m1 = mn1;

        float ps0 = 0.f, ps1 = 0.f;
#pragma unroll
        for (int nf = 0; nf < 8; nf++) {
            const float p0 = __expf(sacc[nf][0] - mn0);
            const float p1 = __expf(sacc[nf][1] - mn0);
            const float p2 = __expf(sacc[nf][2] - mn1);
            const float p3 = __expf(sacc[nf][3] - mn1);
            ps0 += p0 + p1; ps1 += p2 + p3;
            const int cj = nf * 8 + 2 * q4;
            *(float2*)(Sc + r0loc * SCP + cj)       = make_float2(p0, p1);
            *(float2*)(Sc + (r0loc + 8) * SCP + cj) = make_float2(p2, p3);
        }
        ps0 += __shfl_xor_sync(0xffffffffu, ps0, 1);
        ps0 += __shfl_xor_sync(0xffffffffu, ps0, 2);
        ps1 += __shfl_xor_sync(0xffffffffu, ps1, 1);
        ps1 += __shfl_xor_sync(0xffffffffu, ps1, 2);
        l0 = l0 * sc0 + ps0;
        l1 = l1 * sc1 + ps1;

#pragma unroll
        for (int nf = 0; nf < 16; nf++) {
            o[nf][0] *= sc0; o[nf][1] *= sc0;
            o[nf][2] *= sc1; o[nf][3] *= sc1;
        }
        __syncwarp();

#pragma unroll
        for (int kk = 0; kk < 8; kk++) {
            const int kb = kk * 8 + 2 * q4;
            u32 af[4];
            const float2 p0 = *(const float2*)&Sc[r0loc * SCP + kb];
            const float2 p1 = *(const float2*)&Sc[(r0loc + 8) * SCP + kb];
            af[0] = f2tf32(p0.x); af[2] = f2tf32(p0.y);
            af[1] = f2tf32(p1.x); af[3] = f2tf32(p1.y);
#pragma unroll
            for (int nf = 0; nf < 16; nf++) {
                const int d = nf * 8 + g;
                u32 bf[2];
                bf[0] = __float_as_uint(Vs[kb * QPITCH + d]);
                bf[1] = __float_as_uint(Vs[(kb + 1) * QPITCH + d]);
                mma_tf32(o[nf], af, bf);
            }
        }
        __syncthreads();
    }

    const float inv0 = 1.f / l0, inv1 = 1.f / l1;
    float* dst0 = g_ctx + (size_t)gr0 * H_DIM + h * HD;
    float* dst1 = g_ctx + (size_t)gr1 * H_DIM + h * HD;
#pragma unroll
    for (int nf = 0; nf < 16; nf++) {
        const int d = nf * 8 + 2 * q4;
        float2 w0 = make_float2(__uint_as_float(f2tf32(o[nf][0] * inv0)),
                                __uint_as_float(f2tf32(o[nf][1] * inv0)));
        float2 w1 = make_float2(__uint_as_float(f2tf32(o[nf][2] * inv1)),
                                __uint_as_float(f2tf32(o[nf][3] * inv1)));
        *(float2*)(dst0 + d) = w0;
        *(float2*)(dst1 + d) = w1;
    }
}

// ---------------------------------------------------------------------------
extern "C" void kernel_launch(void* const* d_in, const int* in_sizes, int n_in,
                              void* d_out, int out_size)
{
    const float* hidden  = (const float*)d_in[0];
    const float* resid   = (const float*)d_in[1];
    const float* alibi   = (const float*)d_in[2];
    const float* qkv_w   = (const float*)d_in[4];
    const float* qkv_b   = (const float*)d_in[5];
    const float* dense_w = (const float*)d_in[6];
    const float* dense_b = (const float*)d_in[7];
    float* out = (float*)d_out;

    float *fused_p, *ctx_p, *hid_t, *qkvw_t, *densew_t;
    cudaGetSymbolAddress((void**)&fused_p, g_fused);
    cudaGetSymbolAddress((void**)&ctx_p, g_ctx);
    cudaGetSymbolAddress((void**)&hid_t, g_hid_t);
    cudaGetSymbolAddress((void**)&qkvw_t, g_qkvw_t);
    cudaGetSymbolAddress((void**)&densew_t, g_densew_t);

    cudaFuncSetAttribute(gemm_tf32<false, true>,
                         cudaFuncAttributeMaxDynamicSharedMemorySize, GEMM_SMEM);
    cudaFuncSetAttribute(gemm_tf32<true, false>,
                         cudaFuncAttributeMaxDynamicSharedMemorySize, GEMM_SMEM);
    cudaFuncSetAttribute(attn_mma,
                         cudaFuncAttributeMaxDynamicSharedMemorySize, ATTN_SMEM);

    // 0) Pre-convert inputs/weights to tf32-valued fp32
    {
        const int n4h = (S_LEN * H_DIM) / 4;
        cvt_tf32_kernel<<<(n4h + 255) / 256, 256>>>(
            (const float4*)hidden, (float4*)hid_t, n4h);
        const int n4q = (K3 * H_DIM) / 4;
        cvt_tf32_kernel<<<(n4q + 255) / 256, 256>>>(
            (const float4*)qkv_w, (float4*)qkvw_t, n4q);
        const int n4d = (H_DIM * H_DIM) / 4;
        cvt_tf32_kernel<<<(n4d + 255) / 256, 256>>>(
            (const float4*)dense_w, (float4*)densew_t, n4d);
    }

    // 1) fused = hidden @ qkv_w^T + qkv_b (tf32-rounded out)
    //    grid: x = M-tiles (fast) so each wave keeps few B tiles hot in L2
    gemm_tf32<false, true><<<dim3(S_LEN / BM, K3 / BN), 256, GEMM_SMEM>>>(
        hid_t, qkvw_t, qkv_b, nullptr, fused_p, S_LEN, K3, H_DIM);

    // 2) attention -> g_ctx (tf32-rounded out)
    attn_mma<<<dim3(S_LEN / AQM, NHEADS), 256, ATTN_SMEM>>>(alibi);

    // 3) out = ctx @ dense_w^T + dense_b + residual (fp32 out)
    gemm_tf32<true, false><<<dim3(S_LEN / BM, H_DIM / BN), 256, GEMM_SMEM>>>(
        ctx_p, densew_t, dense_b, resid, out, S_LEN, H_DIM, H_DIM);
}

// round 14
// speedup vs baseline: 2.6973x; 1.5732x over previous
#include <cuda_runtime.h>
#include <cuda_fp16.h>
#include <stdint.h>
#include <math.h>

// Problem constants
#define S_LEN   2048
#define H_DIM   4096
#define NHEADS  32
#define HD      128
#define K3      12288            // 3*H
#define INV_NORM 0.08838834764831845f   // 1/sqrt(128)

typedef unsigned int u32;

// Scratch (device globals: allocation-free)
__device__ float  g_fused[(size_t)S_LEN * K3];      // [S, NH, 3, HD] tf32-valued fp32
__device__ __half g_ctx_h[(size_t)S_LEN * H_DIM];   // ctx in half
__device__ __half g_hid_h[(size_t)S_LEN * H_DIM];   // half copy of hidden
__device__ __half g_qkvw_h[(size_t)K3 * H_DIM];     // half copy of qkv_w
__device__ __half g_densew_h[(size_t)H_DIM * H_DIM];// half copy of dense_w

// ---------------------------------------------------------------------------
// Helpers
// ---------------------------------------------------------------------------
__device__ __forceinline__ u32 f2tf32(float x) {
    u32 r;
    asm("cvt.rna.tf32.f32 %0, %1;" : "=r"(r) : "f"(x));
    return r;
}

__device__ __forceinline__ void mma_tf32(float c[4], const u32 a[4],
                                         const u32 b[2]) {
    asm volatile(
        "mma.sync.aligned.m16n8k8.row.col.f32.tf32.tf32.f32 "
        "{%0,%1,%2,%3}, {%4,%5,%6,%7}, {%8,%9}, {%0,%1,%2,%3};"
        : "+f"(c[0]), "+f"(c[1]), "+f"(c[2]), "+f"(c[3])
        : "r"(a[0]), "r"(a[1]), "r"(a[2]), "r"(a[3]), "r"(b[0]), "r"(b[1]));
}

__device__ __forceinline__ void mma_f16(float c[4], const u32 a[4],
                                        const u32 b[2]) {
    asm volatile(
        "mma.sync.aligned.m16n8k16.row.col.f32.f16.f16.f32 "
        "{%0,%1,%2,%3}, {%4,%5,%6,%7}, {%8,%9}, {%0,%1,%2,%3};"
        : "+f"(c[0]), "+f"(c[1]), "+f"(c[2]), "+f"(c[3])
        : "r"(a[0]), "r"(a[1]), "r"(a[2]), "r"(a[3]), "r"(b[0]), "r"(b[1]));
}

__device__ __forceinline__ void cpasync16(void* dst_smem, const void* src) {
    u32 sd = (u32)__cvta_generic_to_shared(dst_smem);
    asm volatile("cp.async.cg.shared.global [%0], [%1], 16;"
                 :: "r"(sd), "l"(src));
}

// Elementwise fp32 -> fp16 (rn)
__global__ __launch_bounds__(256) void cvt_f16_kernel(
    const float4* __restrict__ src, uint2* __restrict__ dst, int n4)
{
    const int i = blockIdx.x * blockDim.x + threadIdx.x;
    if (i < n4) {
        float4 v = src[i];
        __half2 h0 = __floats2half2_rn(v.x, v.y);
        __half2 h1 = __floats2half2_rn(v.z, v.w);
        uint2 o;
        o.x = *(u32*)&h0;
        o.y = *(u32*)&h1;
        dst[i] = o;
    }
}

// ---------------------------------------------------------------------------
// fp16 tensor-core GEMM: C = A @ Bw^T + bias (+resid), fp32 accumulate.
// A/Bw are __half. 128x128 CTA tile, BK=64 halfs, 256 threads, warp 64x32.
// m16n8k16 with k-permutation making fragment k-slots contiguous (LDS.64).
// Pitch 80 halfs (160B): LDS.64 bank set g*40+2q4 mod 32 conflict-free.
// ---------------------------------------------------------------------------
#define BM 128
#define BN 128
#define BKH 64                    // halfs of K per tile
#define HPITCH 80                 // halfs
#define TILE_HALFS (BM * HPITCH)  // 10240 halfs = 20480 B
#define GEMM_SMEM (4 * TILE_HALFS * 2)   // 2 stages x (A+B) = 81920 B

template<bool ADD_RES, bool CVT_OUT>
__global__ __launch_bounds__(256, 2) void gemm_f16(
    const __half* __restrict__ A, const __half* __restrict__ Bw,
    const float* __restrict__ bias, const float* __restrict__ resid,
    float* __restrict__ C, int M, int N, int K)
{
    extern __shared__ __half smh[];
    __half* Abuf[2] = { smh,                  smh + TILE_HALFS };
    __half* Bbuf[2] = { smh + 2 * TILE_HALFS, smh + 3 * TILE_HALFS };

    const int tid  = threadIdx.x;
    const int warp = tid >> 5;
    const int lane = tid & 31;
    const int wm   = (warp & 1) * 64;
    const int wn   = (warp >> 1) * 32;
    const int frow = tid >> 3;          // 0..31? no: 256/8 = 32.. see below
    // fill mapping: 1024 16B-chunks per tile (128 rows x 8 chunks), 4/thread

    const int mt = blockIdx.x;          // M-tile fast -> B tiles L2-resident
    const int nt = blockIdx.y;

    const __half* Ab = A  + (size_t)mt * BM * K;
    const __half* Bb = Bw + (size_t)nt * BN * K;

    float acc[4][4][4];
#pragma unroll
    for (int i = 0; i < 4; i++)
#pragma unroll
        for (int j = 0; j < 4; j++)
#pragma unroll
            for (int r = 0; r < 4; r++) acc[i][j][r] = 0.f;

#pragma unroll
    for (int i = 0; i < 4; i++) {
        const int idx = tid + i * 256;
        const int row = idx >> 3, ch = (idx & 7) * 8;   // 8 halfs = 16B
        cpasync16(&Abuf[0][row * HPITCH + ch], Ab + (size_t)row * K + ch);
        cpasync16(&Bbuf[0][row * HPITCH + ch], Bb + (size_t)row * K + ch);
    }
    asm volatile("cp.async.commit_group;");
    asm volatile("cp.async.wait_group 0;");
    __syncthreads();

    const int NT = K / BKH;
    for (int t = 0; t < NT; t++) {
        const int buf = t & 1;
        if (t + 1 < NT) {
            const int nxt = buf ^ 1;
            const int koff = (t + 1) * BKH;
#pragma unroll
            for (int i = 0; i < 4; i++) {
                const int idx = tid + i * 256;
                const int row = idx >> 3, ch = (idx & 7) * 8;
                cpasync16(&Abuf[nxt][row * HPITCH + ch],
                          Ab + (size_t)row * K + koff + ch);
                cpasync16(&Bbuf[nxt][row * HPITCH + ch],
                          Bb + (size_t)row * K + koff + ch);
            }
        }
        asm volatile("cp.async.commit_group;");

        const __half* As = Abuf[buf];
        const __half* Bs = Bbuf[buf];

#pragma unroll
        for (int kk = 0; kk < 4; kk++) {                 // 4 x k16 = 64 halfs
            const int kb = kk * 16 + 4 * (lane & 3);     // permuted k base
            u32 af[4][4], bf[4][2];
#pragma unroll
            for (int mf = 0; mf < 4; mf++) {
                const int r0 = wm + mf * 16 + (lane >> 2);
                const uint2 x0 = *(const uint2*)&As[r0 * HPITCH + kb];
                const uint2 x1 = *(const uint2*)&As[(r0 + 8) * HPITCH + kb];
                af[mf][0] = x0.x;   // a0,a1: row r,   k {2q4, 2q4+1}
                af[mf][1] = x1.x;   // a2,a3: row r+8
                af[mf][2] = x0.y;   // a4,a5: row r,   k {2q4+8, 2q4+9}
                af[mf][3] = x1.y;   // a6,a7: row r+8
            }
#pragma unroll
            for (int nf = 0; nf < 4; nf++) {
                const int c0 = wn + nf * 8 + (lane >> 2);
                const uint2 y = *(const uint2*)&Bs[c0 * HPITCH + kb];
                bf[nf][0] = y.x;
                bf[nf][1] = y.y;
            }
#pragma unroll
            for (int mf = 0; mf < 4; mf++)
#pragma unroll
                for (int nf = 0; nf < 4; nf++)
                    mma_f16(acc[mf][nf], af[mf], bf[nf]);
        }

        asm volatile("cp.async.wait_group 0;");
        __syncthreads();
    }

#pragma unroll
    for (int mf = 0; mf < 4; mf++) {
        const int row = mt * BM + wm + mf * 16 + (lane >> 2);
#pragma unroll
        for (int nf = 0; nf < 4; nf++) {
            const int col = nt * BN + wn + nf * 8 + 2 * (lane & 3);
            const float b0 = bias[col], b1 = bias[col + 1];
            float v0 = acc[mf][nf][0] + b0;
            float v1 = acc[mf][nf][1] + b1;
            float v2 = acc[mf][nf][2] + b0;
            float v3 = acc[mf][nf][3] + b1;
            if (ADD_RES) {
                v0 += resid[(size_t)row * N + col];
                v1 += resid[(size_t)row * N + col + 1];
                v2 += resid[(size_t)(row + 8) * N + col];
                v3 += resid[(size_t)(row + 8) * N + col + 1];
            }
            if (CVT_OUT) {
                v0 = __uint_as_float(f2tf32(v0));
                v1 = __uint_as_float(f2tf32(v1));
                v2 = __uint_as_float(f2tf32(v2));
                v3 = __uint_as_float(f2tf32(v3));
            }
            *(float2*)(C + (size_t)row * N + col)       = make_float2(v0, v1);
            *(float2*)(C + (size_t)(row + 8) * N + col) = make_float2(v2, v3);
        }
    }
}

// ---------------------------------------------------------------------------
// Tensor-core flash attention (tf32 mma, fp32 softmax). Mainloop unchanged
// from R12/R13 (passing); epilogue now writes half into g_ctx_h.
// ---------------------------------------------------------------------------
#define AQM 128
#define AKT 64
#define QPITCH 132
#define SCP 68
#define NEG_INF -1e30f
#define ATTN_SMEM ((AQM*QPITCH + 2*AKT*QPITCH + AQM*SCP + S_LEN) * 4)  // 178176

__global__ __launch_bounds__(256, 1) void attn_mma(const float* __restrict__ alibi)
{
    extern __shared__ float sm[];
    float* Qs  = sm;
    float* Ks  = Qs + AQM * QPITCH;
    float* Vs  = Ks + AKT * QPITCH;
    float* Sc  = Vs + AKT * QPITCH;
    float* sal = Sc + AQM * SCP;

    const int qt   = (int)gridDim.x - 1 - (int)blockIdx.x;
    const int q0   = qt * AQM;
    const int h    = blockIdx.y;
    const int tid  = threadIdx.x;
    const int w    = tid >> 5;
    const int lane = tid & 31;
    const int g    = lane >> 2;
    const int q4   = lane & 3;

    {
        const float* qbase = g_fused + (size_t)q0 * K3 + h * 384;
#pragma unroll
        for (int i = 0; i < 16; i++) {
            const int idx = tid + i * 256;
            const int r = idx >> 5, c4 = (idx & 31) * 4;
            *(float4*)(Qs + r * QPITCH + c4) =
                *(const float4*)(qbase + (size_t)r * K3 + c4);
        }
        const float* alibi_h = alibi + (size_t)h * S_LEN;
        for (int idx = tid; idx < q0 + AQM; idx += 256)
            sal[idx] = alibi_h[idx];
    }

    const int r0loc = w * 16 + g;
    const int gr0 = q0 + r0loc;
    const int gr1 = gr0 + 8;

    float o[16][4];
#pragma unroll
    for (int nf = 0; nf < 16; nf++)
#pragma unroll
        for (int r = 0; r < 4; r++) o[nf][r] = 0.f;
    float m0 = NEG_INF, m1 = NEG_INF, l0 = 0.f, l1 = 0.f;

    const int nkt = q0 / AKT + 2;
    for (int kt = 0; kt < nkt; kt++) {
        const int kc = kt * AKT;
        {
            const float* kb = g_fused + (size_t)kc * K3 + h * 384 + 128;
#pragma unroll
            for (int i = 0; i < 8; i++) {
                const int idx = tid + i * 256;
                const int r = idx >> 5, c4 = (idx & 31) * 4;
                cpasync16(Ks + r * QPITCH + c4, kb + (size_t)r * K3 + c4);
                cpasync16(Vs + r * QPITCH + c4, kb + (size_t)r * K3 + 128 + c4);
            }
        }
        asm volatile("cp.async.commit_group;");
        asm volatile("cp.async.wait_group 0;");
        __syncthreads();

        float sacc[8][4];
#pragma unroll
        for (int nf = 0; nf < 8; nf++)
#pragma unroll
            for (int r = 0; r < 4; r++) sacc[nf][r] = 0.f;

#pragma unroll
        for (int kk = 0; kk < 16; kk++) {
            const int kb = kk * 8 + 2 * q4;
            u32 af[4];
            const uint2 a0 = *(const uint2*)&Qs[r0loc * QPITCH + kb];
            const uint2 a1 = *(const uint2*)&Qs[(r0loc + 8) * QPITCH + kb];
            af[0] = a0.x; af[2] = a0.y;
            af[1] = a1.x; af[3] = a1.y;
#pragma unroll
            for (int nf = 0; nf < 8; nf++) {
                const int c0 = nf * 8 + g;
                const uint2 b0 = *(const uint2*)&Ks[c0 * QPITCH + kb];
                u32 bf[2];
                bf[0] = b0.x; bf[1] = b0.y;
                mma_tf32(sacc[nf], af, bf);
            }
        }

        float mx0 = NEG_INF, mx1 = NEG_INF;
#pragma unroll
        for (int nf = 0; nf < 8; nf++) {
            const int j0 = kc + nf * 8 + 2 * q4;
            const float a0 = sal[j0], a1 = sal[j0 + 1];
            const float s0 = (j0     <= gr0) ? sacc[nf][0] * INV_NORM + a0 : NEG_INF;
            const float s1 = (j0 + 1 <= gr0) ? sacc[nf][1] * INV_NORM + a1 : NEG_INF;
            const float s2 = (j0     <= gr1) ? sacc[nf][2] * INV_NORM + a0 : NEG_INF;
            const float s3 = (j0 + 1 <= gr1) ? sacc[nf][3] * INV_NORM + a1 : NEG_INF;
            sacc[nf][0] = s0; sacc[nf][1] = s1;
            sacc[nf][2] = s2; sacc[nf][3] = s3;
            mx0 = fmaxf(mx0, fmaxf(s0, s1));
            mx1 = fmaxf(mx1, fmaxf(s2, s3));
        }
        mx0 = fmaxf(mx0, __shfl_xor_sync(0xffffffffu, mx0, 1));
        mx0 = fmaxf(mx0, __shfl_xor_sync(0xffffffffu, mx0, 2));
        mx1 = fmaxf(mx1, __shfl_xor_sync(0xffffffffu, mx1, 1));
        mx1 = fmaxf(mx1, __shfl_xor_sync(0xffffffffu, mx1, 2));

        const float mn0 = fmaxf(m0, mx0), mn1 = fmaxf(m1, mx1);
        const float sc0 = __expf(m0 - mn0), sc1 = __expf(m1 - mn1);
        m0 = mn0; m1 = mn1;

        float ps0 = 0.f, ps1 = 0.f;
#pragma unroll
        for (int nf = 0; nf < 8; nf++) {
            const float p0 = __expf(sacc[nf][0] - mn0);
            const float p1 = __expf(sacc[nf][1] - mn0);
            const float p2 = __expf(sacc[nf][2] - mn1);
            const float p3 = __expf(sacc[nf][3] - mn1);
            ps0 += p0 + p1; ps1 += p2 + p3;
            const int cj = nf * 8 + 2 * q4;
            *(float2*)(Sc + r0loc * SCP + cj)       = make_float2(p0, p1);
            *(float2*)(Sc + (r0loc + 8) * SCP + cj) = make_float2(p2, p3);
        }
        ps0 += __shfl_xor_sync(0xffffffffu, ps0, 1);
        ps0 += __shfl_xor_sync(0xffffffffu, ps0, 2);
        ps1 += __shfl_xor_sync(0xffffffffu, ps1, 1);
        ps1 += __shfl_xor_sync(0xffffffffu, ps1, 2);
        l0 = l0 * sc0 + ps0;
        l1 = l1 * sc1 + ps1;

#pragma unroll
        for (int nf = 0; nf < 16; nf++) {
            o[nf][0] *= sc0; o[nf][1] *= sc0;
            o[nf][2] *= sc1; o[nf][3] *= sc1;
        }
        __syncwarp();

#pragma unroll
        for (int kk = 0; kk < 8; kk++) {
            const int kb = kk * 8 + 2 * q4;
            u32 af[4];
            const float2 p0 = *(const float2*)&Sc[r0loc * SCP + kb];
            const float2 p1 = *(const float2*)&Sc[(r0loc + 8) * SCP + kb];
            af[0] = f2tf32(p0.x); af[2] = f2tf32(p0.y);
            af[1] = f2tf32(p1.x); af[3] = f2tf32(p1.y);
#pragma unroll
            for (int nf = 0; nf < 16; nf++) {
                const int d = nf * 8 + g;
                u32 bf[2];
                bf[0] = __float_as_uint(Vs[kb * QPITCH + d]);
                bf[1] = __float_as_uint(Vs[(kb + 1) * QPITCH + d]);
                mma_tf32(o[nf], af, bf);
            }
        }
        __syncthreads();
    }

    // Normalize + write ctx as half (dense GEMM consumes fp16)
    const float inv0 = 1.f / l0, inv1 = 1.f / l1;
    __half* dst0 = g_ctx_h + (size_t)gr0 * H_DIM + h * HD;
    __half* dst1 = g_ctx_h + (size_t)gr1 * H_DIM + h * HD;
#pragma unroll
    for (int nf = 0; nf < 16; nf++) {
        const int d = nf * 8 + 2 * q4;
        __half2 w0 = __floats2half2_rn(o[nf][0] * inv0, o[nf][1] * inv0);
        __half2 w1 = __floats2half2_rn(o[nf][2] * inv1, o[nf][3] * inv1);
        *(__half2*)(dst0 + d) = w0;
        *(__half2*)(dst1 + d) = w1;
    }
}

// ---------------------------------------------------------------------------
extern "C" void kernel_launch(void* const* d_in, const int* in_sizes, int n_in,
                              void* d_out, int out_size)
{
    const float* hidden  = (const float*)d_in[0];
    const float* resid   = (const float*)d_in[1];
    const float* alibi   = (const float*)d_in[2];
    const float* qkv_w   = (const float*)d_in[4];
    const float* qkv_b   = (const float*)d_in[5];
    const float* dense_w = (const float*)d_in[6];
    const float* dense_b = (const float*)d_in[7];
    float* out = (float*)d_out;

    float *fused_p;
    __half *ctx_h, *hid_h, *qkvw_h, *densew_h;
    cudaGetSymbolAddress((void**)&fused_p, g_fused);
    cudaGetSymbolAddress((void**)&ctx_h, g_ctx_h);
    cudaGetSymbolAddress((void**)&hid_h, g_hid_h);
    cudaGetSymbolAddress((void**)&qkvw_h, g_qkvw_h);
    cudaGetSymbolAddress((void**)&densew_h, g_densew_h);

    cudaFuncSetAttribute(gemm_f16<false, true>,
                         cudaFuncAttributeMaxDynamicSharedMemorySize, GEMM_SMEM);
    cudaFuncSetAttribute(gemm_f16<true, false>,
                         cudaFuncAttributeMaxDynamicSharedMemorySize, GEMM_SMEM);
    cudaFuncSetAttribute(attn_mma,
                         cudaFuncAttributeMaxDynamicSharedMemorySize, ATTN_SMEM);

    // 0) Pre-convert inputs/weights to fp16
    {
        const int n4h = (S_LEN * H_DIM) / 4;
        cvt_f16_kernel<<<(n4h + 255) / 256, 256>>>(
            (const float4*)hidden, (uint2*)hid_h, n4h);
        const int n4q = (K3 * H_DIM) / 4;
        cvt_f16_kernel<<<(n4q + 255) / 256, 256>>>(
            (const float4*)qkv_w, (uint2*)qkvw_h, n4q);
        const int n4d = (H_DIM * H_DIM) / 4;
        cvt_f16_kernel<<<(n4d + 255) / 256, 256>>>(
            (const float4*)dense_w, (uint2*)densew_h, n4d);
    }

    // 1) fused = hidden @ qkv_w^T + qkv_b (fp16 mma, tf32-rounded fp32 out)
    gemm_f16<false, true><<<dim3(S_LEN / BM, K3 / BN), 256, GEMM_SMEM>>>(
        hid_h, qkvw_h, qkv_b, nullptr, fused_p, S_LEN, K3, H_DIM);

    // 2) attention -> g_ctx_h (half out)
    attn_mma<<<dim3(S_LEN / AQM, NHEADS), 256, ATTN_SMEM>>>(alibi);

    // 3) out = ctx @ dense_w^T + dense_b + residual (fp32 out)
    gemm_f16<true, false><<<dim3(S_LEN / BM, H_DIM / BN), 256, GEMM_SMEM>>>(
        ctx_h, densew_h, dense_b, resid, out, S_LEN, H_DIM, H_DIM);
}

// round 15
// speedup vs baseline: 3.3078x; 1.2263x over previous
#include <cuda_runtime.h>
#include <cuda_fp16.h>
#include <stdint.h>
#include <math.h>

// Problem constants
#define S_LEN   2048
#define H_DIM   4096
#define NHEADS  32
#define HD      128
#define K3      12288            // 3*H
#define INV_NORM 0.08838834764831845f   // 1/sqrt(128)

typedef unsigned int u32;

// Scratch (device globals: allocation-free)
__device__ __half g_fused_h[(size_t)S_LEN * K3];    // [S, NH, 3, HD] half
__device__ __half g_ctx_h[(size_t)S_LEN * H_DIM];   // ctx in half
__device__ __half g_hid_h[(size_t)S_LEN * H_DIM];   // half copy of hidden
__device__ __half g_qkvw_h[(size_t)K3 * H_DIM];     // half copy of qkv_w
__device__ __half g_densew_h[(size_t)H_DIM * H_DIM];// half copy of dense_w

// ---------------------------------------------------------------------------
// Helpers
// ---------------------------------------------------------------------------
__device__ __forceinline__ void mma_f16(float c[4], const u32 a[4],
                                        const u32 b[2]) {
    asm volatile(
        "mma.sync.aligned.m16n8k16.row.col.f32.f16.f16.f32 "
        "{%0,%1,%2,%3}, {%4,%5,%6,%7}, {%8,%9}, {%0,%1,%2,%3};"
        : "+f"(c[0]), "+f"(c[1]), "+f"(c[2]), "+f"(c[3])
        : "r"(a[0]), "r"(a[1]), "r"(a[2]), "r"(a[3]), "r"(b[0]), "r"(b[1]));
}

__device__ __forceinline__ void ldsm_x4_trans(u32& r0, u32& r1, u32& r2,
                                              u32& r3, u32 addr) {
    asm volatile(
        "ldmatrix.sync.aligned.m8n8.x4.trans.shared.b16 {%0,%1,%2,%3}, [%4];"
        : "=r"(r0), "=r"(r1), "=r"(r2), "=r"(r3) : "r"(addr));
}

__device__ __forceinline__ void cpasync16(void* dst_smem, const void* src) {
    u32 sd = (u32)__cvta_generic_to_shared(dst_smem);
    asm volatile("cp.async.cg.shared.global [%0], [%1], 16;"
                 :: "r"(sd), "l"(src));
}

// Elementwise fp32 -> fp16 (rn)
__global__ __launch_bounds__(256) void cvt_f16_kernel(
    const float4* __restrict__ src, uint2* __restrict__ dst, int n4)
{
    const int i = blockIdx.x * blockDim.x + threadIdx.x;
    if (i < n4) {
        float4 v = src[i];
        __half2 h0 = __floats2half2_rn(v.x, v.y);
        __half2 h1 = __floats2half2_rn(v.z, v.w);
        uint2 o;
        o.x = *(u32*)&h0;
        o.y = *(u32*)&h1;
        dst[i] = o;
    }
}

// ---------------------------------------------------------------------------
// fp16 tensor-core GEMM: C = A @ Bw^T + bias (+resid), fp32 accumulate.
// 128x128 CTA, BK=64 halfs, 256 threads, warp 64x32, m16n8k16 paired-k.
// HALF_OUT: C is __half (for tensors consumed by later mma); else fp32.
// ---------------------------------------------------------------------------
#define BM 128
#define BN 128
#define BKH 64
#define HPITCH 80
#define TILE_HALFS (BM * HPITCH)
#define GEMM_SMEM (4 * TILE_HALFS * 2)   // 81920 B

template<bool ADD_RES, bool HALF_OUT>
__global__ __launch_bounds__(256, 2) void gemm_f16(
    const __half* __restrict__ A, const __half* __restrict__ Bw,
    const float* __restrict__ bias, const float* __restrict__ resid,
    void* __restrict__ Cv, int M, int N, int K)
{
    extern __shared__ __half smh[];
    __half* Abuf[2] = { smh,                  smh + TILE_HALFS };
    __half* Bbuf[2] = { smh + 2 * TILE_HALFS, smh + 3 * TILE_HALFS };

    const int tid  = threadIdx.x;
    const int warp = tid >> 5;
    const int lane = tid & 31;
    const int wm   = (warp & 1) * 64;
    const int wn   = (warp >> 1) * 32;

    const int mt = blockIdx.x;          // M-tile fast -> B tiles L2-resident
    const int nt = blockIdx.y;

    const __half* Ab = A  + (size_t)mt * BM * K;
    const __half* Bb = Bw + (size_t)nt * BN * K;

    float acc[4][4][4];
#pragma unroll
    for (int i = 0; i < 4; i++)
#pragma unroll
        for (int j = 0; j < 4; j++)
#pragma unroll
            for (int r = 0; r < 4; r++) acc[i][j][r] = 0.f;

#pragma unroll
    for (int i = 0; i < 4; i++) {
        const int idx = tid + i * 256;
        const int row = idx >> 3, ch = (idx & 7) * 8;
        cpasync16(&Abuf[0][row * HPITCH + ch], Ab + (size_t)row * K + ch);
        cpasync16(&Bbuf[0][row * HPITCH + ch], Bb + (size_t)row * K + ch);
    }
    asm volatile("cp.async.commit_group;");
    asm volatile("cp.async.wait_group 0;");
    __syncthreads();

    const int NT = K / BKH;
    for (int t = 0; t < NT; t++) {
        const int buf = t & 1;
        if (t + 1 < NT) {
            const int nxt = buf ^ 1;
            const int koff = (t + 1) * BKH;
#pragma unroll
            for (int i = 0; i < 4; i++) {
                const int idx = tid + i * 256;
                const int row = idx >> 3, ch = (idx & 7) * 8;
                cpasync16(&Abuf[nxt][row * HPITCH + ch],
                          Ab + (size_t)row * K + koff + ch);
                cpasync16(&Bbuf[nxt][row * HPITCH + ch],
                          Bb + (size_t)row * K + koff + ch);
            }
        }
        asm volatile("cp.async.commit_group;");

        const __half* As = Abuf[buf];
        const __half* Bs = Bbuf[buf];

#pragma unroll
        for (int kk = 0; kk < 4; kk++) {
            const int kb = kk * 16 + 4 * (lane & 3);
            u32 af[4][4], bf[4][2];
#pragma unroll
            for (int mf = 0; mf < 4; mf++) {
                const int r0 = wm + mf * 16 + (lane >> 2);
                const uint2 x0 = *(const uint2*)&As[r0 * HPITCH + kb];
                const uint2 x1 = *(const uint2*)&As[(r0 + 8) * HPITCH + kb];
                af[mf][0] = x0.x;
                af[mf][1] = x1.x;
                af[mf][2] = x0.y;
                af[mf][3] = x1.y;
            }
#pragma unroll
            for (int nf = 0; nf < 4; nf++) {
                const int c0 = wn + nf * 8 + (lane >> 2);
                const uint2 y = *(const uint2*)&Bs[c0 * HPITCH + kb];
                bf[nf][0] = y.x;
                bf[nf][1] = y.y;
            }
#pragma unroll
            for (int mf = 0; mf < 4; mf++)
#pragma unroll
                for (int nf = 0; nf < 4; nf++)
                    mma_f16(acc[mf][nf], af[mf], bf[nf]);
        }

        asm volatile("cp.async.wait_group 0;");
        __syncthreads();
    }

#pragma unroll
    for (int mf = 0; mf < 4; mf++) {
        const int row = mt * BM + wm + mf * 16 + (lane >> 2);
#pragma unroll
        for (int nf = 0; nf < 4; nf++) {
            const int col = nt * BN + wn + nf * 8 + 2 * (lane & 3);
            const float b0 = bias[col], b1 = bias[col + 1];
            float v0 = acc[mf][nf][0] + b0;
            float v1 = acc[mf][nf][1] + b1;
            float v2 = acc[mf][nf][2] + b0;
            float v3 = acc[mf][nf][3] + b1;
            if (ADD_RES) {
                v0 += resid[(size_t)row * N + col];
                v1 += resid[(size_t)row * N + col + 1];
                v2 += resid[(size_t)(row + 8) * N + col];
                v3 += resid[(size_t)(row + 8) * N + col + 1];
            }
            if (HALF_OUT) {
                __half* Ch = (__half*)Cv;
                *(__half2*)(Ch + (size_t)row * N + col) =
                    __floats2half2_rn(v0, v1);
                *(__half2*)(Ch + (size_t)(row + 8) * N + col) =
                    __floats2half2_rn(v2, v3);
            } else {
                float* C = (float*)Cv;
                *(float2*)(C + (size_t)row * N + col)       = make_float2(v0, v1);
                *(float2*)(C + (size_t)(row + 8) * N + col) = make_float2(v2, v3);
            }
        }
    }
}

// ---------------------------------------------------------------------------
// fp16 tensor-core flash attention (fp32 softmax, causal + alibi).
// CTA: 128 q-rows x 64-kv tiles, 8 warps. QK: paired-k LDS.64 frags.
// PV: P in half smem, V B-frags via ldmatrix.x4.trans on row-major V.
// ---------------------------------------------------------------------------
#define AQM 128
#define AKT 64
#define QKP 144     // Q/K pitch (halfs): (row*72 + k/2) banks conflict-free
#define VP  136     // V pitch (halfs): row stride = 4 banks, ldmatrix-clean
#define SCP 72      // P pitch (halfs): row stride = 36 halfs -> 4-bank step
#define NEG_INF -1e30f
// smem: Q 36864 + K 18432 + V 17408 + Sc 18432 + sal 8192 = 99328 B
#define ATTN_SMEM (AQM*QKP*2 + AKT*QKP*2 + AKT*VP*2 + AQM*SCP*2 + S_LEN*4)

__global__ __launch_bounds__(256, 1) void attn_mma(const float* __restrict__ alibi)
{
    extern __shared__ __align__(16) char smraw[];
    __half* Qs  = (__half*)smraw;
    __half* Ks  = Qs + AQM * QKP;
    __half* Vs  = Ks + AKT * QKP;
    __half* Sc  = Vs + AKT * VP;
    float*  sal = (float*)(Sc + AQM * SCP);

    const int qt   = (int)gridDim.x - 1 - (int)blockIdx.x;  // heavy tiles first
    const int q0   = qt * AQM;
    const int h    = blockIdx.y;
    const int tid  = threadIdx.x;
    const int w    = tid >> 5;
    const int lane = tid & 31;
    const int g    = lane >> 2;
    const int q4   = lane & 3;

    const u32 vs_base = (u32)__cvta_generic_to_shared(Vs);

    // Load Q tile (128 x 128 halfs) + alibi row
    {
        const __half* qb = g_fused_h + (size_t)q0 * K3 + h * 384;
#pragma unroll
        for (int i = 0; i < 8; i++) {
            const int idx = tid + i * 256;
            const int r = idx >> 4, c8 = (idx & 15) * 8;
            cpasync16(Qs + r * QKP + c8, qb + (size_t)r * K3 + c8);
        }
        asm volatile("cp.async.commit_group;");
        const float* alibi_h = alibi + (size_t)h * S_LEN;
        for (int idx = tid; idx < q0 + AQM; idx += 256)
            sal[idx] = alibi_h[idx];
    }

    const int r0loc = w * 16 + g;
    const int gr0 = q0 + r0loc;
    const int gr1 = gr0 + 8;

    float o[16][4];
#pragma unroll
    for (int nf = 0; nf < 16; nf++)
#pragma unroll
        for (int r = 0; r < 4; r++) o[nf][r] = 0.f;
    float m0 = NEG_INF, m1 = NEG_INF, l0 = 0.f, l1 = 0.f;

    const int nkt = q0 / AKT + 2;
    for (int kt = 0; kt < nkt; kt++) {
        const int kc = kt * AKT;
        // Fill K/V (64 x 128 halfs each)
        {
            const __half* kb = g_fused_h + (size_t)kc * K3 + h * 384 + 128;
#pragma unroll
            for (int i = 0; i < 4; i++) {
                const int idx = tid + i * 256;
                const int r = idx >> 4, c8 = (idx & 15) * 8;
                cpasync16(Ks + r * QKP + c8, kb + (size_t)r * K3 + c8);
                cpasync16(Vs + r * VP + c8, kb + (size_t)r * K3 + 128 + c8);
            }
        }
        asm volatile("cp.async.commit_group;");
        asm volatile("cp.async.wait_group 0;");
        __syncthreads();

        // S = Q K^T (fp16 m16n8k16, paired-k permutation on HD)
        float sacc[8][4];
#pragma unroll
        for (int nf = 0; nf < 8; nf++)
#pragma unroll
            for (int r = 0; r < 4; r++) sacc[nf][r] = 0.f;

#pragma unroll
        for (int kk = 0; kk < 8; kk++) {
            const int kb = kk * 16 + 4 * q4;
            u32 af[4];
            const uint2 x0 = *(const uint2*)&Qs[r0loc * QKP + kb];
            const uint2 x1 = *(const uint2*)&Qs[(r0loc + 8) * QKP + kb];
            af[0] = x0.x; af[1] = x1.x; af[2] = x0.y; af[3] = x1.y;
#pragma unroll
            for (int nf = 0; nf < 8; nf++) {
                const int c0 = nf * 8 + g;
                const uint2 y = *(const uint2*)&Ks[c0 * QKP + kb];
                u32 bf[2];
                bf[0] = y.x; bf[1] = y.y;
                mma_f16(sacc[nf], af, bf);
            }
        }

        // Online softmax (fp32), P -> half smem
        float mx0 = NEG_INF, mx1 = NEG_INF;
#pragma unroll
        for (int nf = 0; nf < 8; nf++) {
            const int j0 = kc + nf * 8 + 2 * q4;
            const float a0 = sal[j0], a1 = sal[j0 + 1];
            const float s0 = (j0     <= gr0) ? sacc[nf][0] * INV_NORM + a0 : NEG_INF;
            const float s1 = (j0 + 1 <= gr0) ? sacc[nf][1] * INV_NORM + a1 : NEG_INF;
            const float s2 = (j0     <= gr1) ? sacc[nf][2] * INV_NORM + a0 : NEG_INF;
            const float s3 = (j0 + 1 <= gr1) ? sacc[nf][3] * INV_NORM + a1 : NEG_INF;
            sacc[nf][0] = s0; sacc[nf][1] = s1;
            sacc[nf][2] = s2; sacc[nf][3] = s3;
            mx0 = fmaxf(mx0, fmaxf(s0, s1));
            mx1 = fmaxf(mx1, fmaxf(s2, s3));
        }
        mx0 = fmaxf(mx0, __shfl_xor_sync(0xffffffffu, mx0, 1));
        mx0 = fmaxf(mx0, __shfl_xor_sync(0xffffffffu, mx0, 2));
        mx1 = fmaxf(mx1, __shfl_xor_sync(0xffffffffu, mx1, 1));
        mx1 = fmaxf(mx1, __shfl_xor_sync(0xffffffffu, mx1, 2));

        const float mn0 = fmaxf(m0, mx0), mn1 = fmaxf(m1, mx1);
        const float sc0 = __expf(m0 - mn0), sc1 = __expf(m1 - mn1);
        m0 = mn0; m1 = mn1;

        float ps0 = 0.f, ps1 = 0.f;
#pragma unroll
        for (int nf = 0; nf < 8; nf++) {
            const float p0 = __expf(sacc[nf][0] - mn0);
            const float p1 = __expf(sacc[nf][1] - mn0);
            const float p2 = __expf(sacc[nf][2] - mn1);
            const float p3 = __expf(sacc[nf][3] - mn1);
            ps0 += p0 + p1; ps1 += p2 + p3;
            const int cj = nf * 8 + 2 * q4;
            *(__half2*)(Sc + r0loc * SCP + cj)       = __floats2half2_rn(p0, p1);
            *(__half2*)(Sc + (r0loc + 8) * SCP + cj) = __floats2half2_rn(p2, p3);
        }
        ps0 += __shfl_xor_sync(0xffffffffu, ps0, 1);
        ps0 += __shfl_xor_sync(0xffffffffu, ps0, 2);
        ps1 += __shfl_xor_sync(0xffffffffu, ps1, 1);
        ps1 += __shfl_xor_sync(0xffffffffu, ps1, 2);
        l0 = l0 * sc0 + ps0;
        l1 = l1 * sc1 + ps1;

#pragma unroll
        for (int nf = 0; nf < 16; nf++) {
            o[nf][0] *= sc0; o[nf][1] *= sc0;
            o[nf][2] *= sc1; o[nf][3] *= sc1;
        }
        __syncwarp();   // order P stores before frag reloads (warp-private rows)

        // O += P V : A from Sc (natural k layout), B via ldmatrix.x4.trans
#pragma unroll
        for (int kk = 0; kk < 4; kk++) {
            const int k0 = kk * 16;
            u32 af[4];
            af[0] = *(const u32*)&Sc[r0loc * SCP + k0 + 2 * q4];
            af[1] = *(const u32*)&Sc[(r0loc + 8) * SCP + k0 + 2 * q4];
            af[2] = *(const u32*)&Sc[r0loc * SCP + k0 + 8 + 2 * q4];
            af[3] = *(const u32*)&Sc[(r0loc + 8) * SCP + k0 + 8 + 2 * q4];
            const u32 vrow = k0 + (lane & 15);
            const u32 vcol8 = (lane >> 4) * 8;
#pragma unroll
            for (int nf2 = 0; nf2 < 8; nf2++) {
                u32 b0, b1, b2, b3;
                ldsm_x4_trans(b0, b1, b2, b3,
                              vs_base + (vrow * VP + nf2 * 16 + vcol8) * 2);
                u32 bf0[2] = { b0, b1 };
                u32 bf1[2] = { b2, b3 };
                mma_f16(o[nf2 * 2],     af, bf0);
                mma_f16(o[nf2 * 2 + 1], af, bf1);
            }
        }
        __syncthreads();   // all reads done before next K/V fill
    }

    // Normalize + write ctx as half (dense GEMM consumes fp16)
    const float inv0 = 1.f / l0, inv1 = 1.f / l1;
    __half* dst0 = g_ctx_h + (size_t)gr0 * H_DIM + h * HD;
    __half* dst1 = g_ctx_h + (size_t)gr1 * H_DIM + h * HD;
#pragma unroll
    for (int nf = 0; nf < 16; nf++) {
        const int d = nf * 8 + 2 * q4;
        *(__half2*)(dst0 + d) = __floats2half2_rn(o[nf][0] * inv0, o[nf][1] * inv0);
        *(__half2*)(dst1 + d) = __floats2half2_rn(o[nf][2] * inv1, o[nf][3] * inv1);
    }
}

// ---------------------------------------------------------------------------
extern "C" void kernel_launch(void* const* d_in, const int* in_sizes, int n_in,
                              void* d_out, int out_size)
{
    const float* hidden  = (const float*)d_in[0];
    const float* resid   = (const float*)d_in[1];
    const float* alibi   = (const float*)d_in[2];
    const float* qkv_w   = (const float*)d_in[4];
    const float* qkv_b   = (const float*)d_in[5];
    const float* dense_w = (const float*)d_in[6];
    const float* dense_b = (const float*)d_in[7];
    float* out = (float*)d_out;

    __half *fused_h, *ctx_h, *hid_h, *qkvw_h, *densew_h;
    cudaGetSymbolAddress((void**)&fused_h, g_fused_h);
    cudaGetSymbolAddress((void**)&ctx_h, g_ctx_h);
    cudaGetSymbolAddress((void**)&hid_h, g_hid_h);
    cudaGetSymbolAddress((void**)&qkvw_h, g_qkvw_h);
    cudaGetSymbolAddress((void**)&densew_h, g_densew_h);

    cudaFuncSetAttribute(gemm_f16<false, true>,
                         cudaFuncAttributeMaxDynamicSharedMemorySize, GEMM_SMEM);
    cudaFuncSetAttribute(gemm_f16<true, false>,
                         cudaFuncAttributeMaxDynamicSharedMemorySize, GEMM_SMEM);
    cudaFuncSetAttribute(attn_mma,
                         cudaFuncAttributeMaxDynamicSharedMemorySize, ATTN_SMEM);

    // 0) Pre-convert inputs/weights to fp16
    {
        const int n4h = (S_LEN * H_DIM) / 4;
        cvt_f16_kernel<<<(n4h + 255) / 256, 256>>>(
            (const float4*)hidden, (uint2*)hid_h, n4h);
        const int n4q = (K3 * H_DIM) / 4;
        cvt_f16_kernel<<<(n4q + 255) / 256, 256>>>(
            (const float4*)qkv_w, (uint2*)qkvw_h, n4q);
        const int n4d = (H_DIM * H_DIM) / 4;
        cvt_f16_kernel<<<(n4d + 255) / 256, 256>>>(
            (const float4*)dense_w, (uint2*)densew_h, n4d);
    }

    // 1) fused = hidden @ qkv_w^T + qkv_b (fp16 mma, half out)
    gemm_f16<false, true><<<dim3(S_LEN / BM, K3 / BN), 256, GEMM_SMEM>>>(
        hid_h, qkvw_h, qkv_b, nullptr, fused_h, S_LEN, K3, H_DIM);

    // 2) attention -> g_ctx_h (half out)
    attn_mma<<<dim3(S_LEN / AQM, NHEADS), 256, ATTN_SMEM>>>(alibi);

    // 3) out = ctx @ dense_w^T + dense_b + residual (fp32 out)
    gemm_f16<true, false><<<dim3(S_LEN / BM, H_DIM / BN), 256, GEMM_SMEM>>>(
        ctx_h, densew_h, dense_b, resid, out, S_LEN, H_DIM, H_DIM);
}

// round 16
// speedup vs baseline: 3.7078x; 1.1209x over previous
#include <cuda_runtime.h>
#include <cuda_fp16.h>
#include <stdint.h>
#include <math.h>

// Problem constants
#define S_LEN   2048
#define H_DIM   4096
#define NHEADS  32
#define HD      128
#define K3      12288            // 3*H
#define INV_NORM 0.08838834764831845f   // 1/sqrt(128)

typedef unsigned int u32;

// Scratch (device globals: allocation-free)
__device__ __half g_fused_h[(size_t)S_LEN * K3];    // [S, NH, 3, HD] half
__device__ __half g_ctx_h[(size_t)S_LEN * H_DIM];   // ctx in half
__device__ __half g_hid_h[(size_t)S_LEN * H_DIM];   // half copy of hidden
__device__ __half g_qkvw_h[(size_t)K3 * H_DIM];     // half copy of qkv_w
__device__ __half g_densew_h[(size_t)H_DIM * H_DIM];// half copy of dense_w

// ---------------------------------------------------------------------------
// Helpers
// ---------------------------------------------------------------------------
__device__ __forceinline__ void mma_f16(float c[4], const u32 a[4],
                                        const u32 b[2]) {
    asm volatile(
        "mma.sync.aligned.m16n8k16.row.col.f32.f16.f16.f32 "
        "{%0,%1,%2,%3}, {%4,%5,%6,%7}, {%8,%9}, {%0,%1,%2,%3};"
        : "+f"(c[0]), "+f"(c[1]), "+f"(c[2]), "+f"(c[3])
        : "r"(a[0]), "r"(a[1]), "r"(a[2]), "r"(a[3]), "r"(b[0]), "r"(b[1]));
}

__device__ __forceinline__ void ldsm_x4(u32& r0, u32& r1, u32& r2, u32& r3,
                                        u32 addr) {
    asm volatile(
        "ldmatrix.sync.aligned.m8n8.x4.shared.b16 {%0,%1,%2,%3}, [%4];"
        : "=r"(r0), "=r"(r1), "=r"(r2), "=r"(r3) : "r"(addr));
}

__device__ __forceinline__ void ldsm_x4_trans(u32& r0, u32& r1, u32& r2,
                                              u32& r3, u32 addr) {
    asm volatile(
        "ldmatrix.sync.aligned.m8n8.x4.trans.shared.b16 {%0,%1,%2,%3}, [%4];"
        : "=r"(r0), "=r"(r1), "=r"(r2), "=r"(r3) : "r"(addr));
}

__device__ __forceinline__ void cpasync16(void* dst_smem, const void* src) {
    u32 sd = (u32)__cvta_generic_to_shared(dst_smem);
    asm volatile("cp.async.cg.shared.global [%0], [%1], 16;"
                 :: "r"(sd), "l"(src));
}

// Elementwise fp32 -> fp16 (rn)
__global__ __launch_bounds__(256) void cvt_f16_kernel(
    const float4* __restrict__ src, uint2* __restrict__ dst, int n4)
{
    const int i = blockIdx.x * blockDim.x + threadIdx.x;
    if (i < n4) {
        float4 v = src[i];
        __half2 h0 = __floats2half2_rn(v.x, v.y);
        __half2 h1 = __floats2half2_rn(v.z, v.w);
        uint2 o;
        o.x = *(u32*)&h0;
        o.y = *(u32*)&h1;
        dst[i] = o;
    }
}

// ---------------------------------------------------------------------------
// fp16 tensor-core GEMM: C = A @ Bw^T + bias (+resid), fp32 accumulate.
// 128x128 CTA, BK=64 halfs (128B rows), 256 threads, warp 64x32.
// Fragments via ldmatrix.x4 on xor-swizzled smem (chunk ^= row&7):
// conflict-free, 6 ldmatrix + 16 HMMA per k16-step.
// ---------------------------------------------------------------------------
#define BM 128
#define BN 128
#define BKH 64                    // halfs per K-tile row (128 B)
#define TILE_HALFS (BM * BKH)     // 8192 halfs = 16 KB
#define GEMM_SMEM (4 * TILE_HALFS * 2)   // 2 stages x (A+B) = 65536 B

// swizzled half-offset within a tile: row 128B, chunk = 16B unit
__device__ __forceinline__ int swz(int row, int chunk) {
    return row * BKH + ((chunk ^ (row & 7)) << 3);
}

template<bool ADD_RES, bool HALF_OUT>
__global__ __launch_bounds__(256, 2) void gemm_f16(
    const __half* __restrict__ A, const __half* __restrict__ Bw,
    const float* __restrict__ bias, const float* __restrict__ resid,
    void* __restrict__ Cv, int M, int N, int K)
{
    extern __shared__ __half smh[];
    __half* Abuf[2] = { smh,                  smh + TILE_HALFS };
    __half* Bbuf[2] = { smh + 2 * TILE_HALFS, smh + 3 * TILE_HALFS };

    const int tid  = threadIdx.x;
    const int warp = tid >> 5;
    const int lane = tid & 31;
    const int wm   = (warp & 1) * 64;
    const int wn   = (warp >> 1) * 32;

    const int mt = blockIdx.x;          // M-tile fast -> B tiles L2-resident
    const int nt = blockIdx.y;

    const __half* Ab = A  + (size_t)mt * BM * K;
    const __half* Bb = Bw + (size_t)nt * BN * K;

    float acc[4][4][4];
#pragma unroll
    for (int i = 0; i < 4; i++)
#pragma unroll
        for (int j = 0; j < 4; j++)
#pragma unroll
            for (int r = 0; r < 4; r++) acc[i][j][r] = 0.f;

    // Prologue fill (stage 0), swizzled stores
#pragma unroll
    for (int i = 0; i < 4; i++) {
        const int idx = tid + i * 256;
        const int row = idx >> 3, ch = idx & 7;
        cpasync16(&Abuf[0][swz(row, ch)], Ab + (size_t)row * K + ch * 8);
        cpasync16(&Bbuf[0][swz(row, ch)], Bb + (size_t)row * K + ch * 8);
    }
    asm volatile("cp.async.commit_group;");
    asm volatile("cp.async.wait_group 0;");
    __syncthreads();

    // ldmatrix lane decode (constant per thread)
    const int lmi = lane >> 3;          // matrix index 0..3
    const int lmr = lane & 7;           // row within matrix

    const int NT = K / BKH;
    for (int t = 0; t < NT; t++) {
        const int buf = t & 1;
        if (t + 1 < NT) {
            const int nxt = buf ^ 1;
            const int koff = (t + 1) * BKH;
#pragma unroll
            for (int i = 0; i < 4; i++) {
                const int idx = tid + i * 256;
                const int row = idx >> 3, ch = idx & 7;
                cpasync16(&Abuf[nxt][swz(row, ch)],
                          Ab + (size_t)row * K + koff + ch * 8);
                cpasync16(&Bbuf[nxt][swz(row, ch)],
                          Bb + (size_t)row * K + koff + ch * 8);
            }
        }
        asm volatile("cp.async.commit_group;");

        const u32 as_base = (u32)__cvta_generic_to_shared(Abuf[buf]);
        const u32 bs_base = (u32)__cvta_generic_to_shared(Bbuf[buf]);

#pragma unroll
        for (int kk = 0; kk < 4; kk++) {
            u32 af[4][4], bf[4][2];
            // A: one ldmatrix.x4 per mf tile (m0=rows0-7/klo, m1=rows8-15/klo,
            //    m2=rows0-7/khi, m3=rows8-15/khi -> canonical a-frag order)
#pragma unroll
            for (int mf = 0; mf < 4; mf++) {
                const int row = wm + mf * 16 + ((lmi & 1) << 3) + lmr;
                const int ch  = 2 * kk + (lmi >> 1);
                ldsm_x4(af[mf][0], af[mf][1], af[mf][2], af[mf][3],
                        as_base + swz(row, ch) * 2);
            }
            // B: two ldmatrix.x4, each covers 2 n-frags x 2 k-chunks
#pragma unroll
            for (int p = 0; p < 2; p++) {
                const int nf  = 2 * p + (lmi >> 1);
                const int ch  = 2 * kk + (lmi & 1);
                const int row = wn + nf * 8 + lmr;
                u32 b0, b1, b2, b3;
                ldsm_x4(b0, b1, b2, b3, bs_base + swz(row, ch) * 2);
                bf[2 * p][0]     = b0; bf[2 * p][1]     = b1;
                bf[2 * p + 1][0] = b2; bf[2 * p + 1][1] = b3;
            }
#pragma unroll
            for (int mf = 0; mf < 4; mf++)
#pragma unroll
                for (int nf = 0; nf < 4; nf++)
                    mma_f16(acc[mf][nf], af[mf], bf[nf]);
        }

        asm volatile("cp.async.wait_group 0;");
        __syncthreads();
    }

#pragma unroll
    for (int mf = 0; mf < 4; mf++) {
        const int row = mt * BM + wm + mf * 16 + (lane >> 2);
#pragma unroll
        for (int nf = 0; nf < 4; nf++) {
            const int col = nt * BN + wn + nf * 8 + 2 * (lane & 3);
            const float b0 = bias[col], b1 = bias[col + 1];
            float v0 = acc[mf][nf][0] + b0;
            float v1 = acc[mf][nf][1] + b1;
            float v2 = acc[mf][nf][2] + b0;
            float v3 = acc[mf][nf][3] + b1;
            if (ADD_RES) {
                v0 += resid[(size_t)row * N + col];
                v1 += resid[(size_t)row * N + col + 1];
                v2 += resid[(size_t)(row + 8) * N + col];
                v3 += resid[(size_t)(row + 8) * N + col + 1];
            }
            if (HALF_OUT) {
                __half* Ch = (__half*)Cv;
                *(__half2*)(Ch + (size_t)row * N + col) =
                    __floats2half2_rn(v0, v1);
                *(__half2*)(Ch + (size_t)(row + 8) * N + col) =
                    __floats2half2_rn(v2, v3);
            } else {
                float* C = (float*)Cv;
                *(float2*)(C + (size_t)row * N + col)       = make_float2(v0, v1);
                *(float2*)(C + (size_t)(row + 8) * N + col) = make_float2(v2, v3);
            }
        }
    }
}

// ---------------------------------------------------------------------------
// fp16 tensor-core flash attention (unchanged from R15, passing).
// ---------------------------------------------------------------------------
#define AQM 128
#define AKT 64
#define QKP 144
#define VP  136
#define SCP 72
#define NEG_INF -1e30f
#define ATTN_SMEM (AQM*QKP*2 + AKT*QKP*2 + AKT*VP*2 + AQM*SCP*2 + S_LEN*4)

__global__ __launch_bounds__(256, 1) void attn_mma(const float* __restrict__ alibi)
{
    extern __shared__ __align__(16) char smraw[];
    __half* Qs  = (__half*)smraw;
    __half* Ks  = Qs + AQM * QKP;
    __half* Vs  = Ks + AKT * QKP;
    __half* Sc  = Vs + AKT * VP;
    float*  sal = (float*)(Sc + AQM * SCP);

    const int qt   = (int)gridDim.x - 1 - (int)blockIdx.x;
    const int q0   = qt * AQM;
    const int h    = blockIdx.y;
    const int tid  = threadIdx.x;
    const int w    = tid >> 5;
    const int lane = tid & 31;
    const int g    = lane >> 2;
    const int q4   = lane & 3;

    const u32 vs_base = (u32)__cvta_generic_to_shared(Vs);

    {
        const __half* qb = g_fused_h + (size_t)q0 * K3 + h * 384;
#pragma unroll
        for (int i = 0; i < 8; i++) {
            const int idx = tid + i * 256;
            const int r = idx >> 4, c8 = (idx & 15) * 8;
            cpasync16(Qs + r * QKP + c8, qb + (size_t)r * K3 + c8);
        }
        asm volatile("cp.async.commit_group;");
        const float* alibi_h = alibi + (size_t)h * S_LEN;
        for (int idx = tid; idx < q0 + AQM; idx += 256)
            sal[idx] = alibi_h[idx];
    }

    const int r0loc = w * 16 + g;
    const int gr0 = q0 + r0loc;
    const int gr1 = gr0 + 8;

    float o[16][4];
#pragma unroll
    for (int nf = 0; nf < 16; nf++)
#pragma unroll
        for (int r = 0; r < 4; r++) o[nf][r] = 0.f;
    float m0 = NEG_INF, m1 = NEG_INF, l0 = 0.f, l1 = 0.f;

    const int nkt = q0 / AKT + 2;
    for (int kt = 0; kt < nkt; kt++) {
        const int kc = kt * AKT;
        {
            const __half* kb = g_fused_h + (size_t)kc * K3 + h * 384 + 128;
#pragma unroll
            for (int i = 0; i < 4; i++) {
                const int idx = tid + i * 256;
                const int r = idx >> 4, c8 = (idx & 15) * 8;
                cpasync16(Ks + r * QKP + c8, kb + (size_t)r * K3 + c8);
                cpasync16(Vs + r * VP + c8, kb + (size_t)r * K3 + 128 + c8);
            }
        }
        asm volatile("cp.async.commit_group;");
        asm volatile("cp.async.wait_group 0;");
        __syncthreads();

        float sacc[8][4];
#pragma unroll
        for (int nf = 0; nf < 8; nf++)
#pragma unroll
            for (int r = 0; r < 4; r++) sacc[nf][r] = 0.f;

#pragma unroll
        for (int kk = 0; kk < 8; kk++) {
            const int kb = kk * 16 + 4 * q4;
            u32 af[4];
            const uint2 x0 = *(const uint2*)&Qs[r0loc * QKP + kb];
            const uint2 x1 = *(const uint2*)&Qs[(r0loc + 8) * QKP + kb];
            af[0] = x0.x; af[1] = x1.x; af[2] = x0.y; af[3] = x1.y;
#pragma unroll
            for (int nf = 0; nf < 8; nf++) {
                const int c0 = nf * 8 + g;
                const uint2 y = *(const uint2*)&Ks[c0 * QKP + kb];
                u32 bf[2];
                bf[0] = y.x; bf[1] = y.y;
                mma_f16(sacc[nf], af, bf);
            }
        }

        float mx0 = NEG_INF, mx1 = NEG_INF;
#pragma unroll
        for (int nf = 0; nf < 8; nf++) {
            const int j0 = kc + nf * 8 + 2 * q4;
            const float a0 = sal[j0], a1 = sal[j0 + 1];
            const float s0 = (j0     <= gr0) ? sacc[nf][0] * INV_NORM + a0 : NEG_INF;
            const float s1 = (j0 + 1 <= gr0) ? sacc[nf][1] * INV_NORM + a1 : NEG_INF;
            const float s2 = (j0     <= gr1) ? sacc[nf][2] * INV_NORM + a0 : NEG_INF;
            const float s3 = (j0 + 1 <= gr1) ? sacc[nf][3] * INV_NORM + a1 : NEG_INF;
            sacc[nf][0] = s0; sacc[nf][1] = s1;
            sacc[nf][2] = s2; sacc[nf][3] = s3;
            mx0 = fmaxf(mx0, fmaxf(s0, s1));
            mx1 = fmaxf(mx1, fmaxf(s2, s3));
        }
        mx0 = fmaxf(mx0, __shfl_xor_sync(0xffffffffu, mx0, 1));
        mx0 = fmaxf(mx0, __shfl_xor_sync(0xffffffffu, mx0, 2));
        mx1 = fmaxf(mx1, __shfl_xor_sync(0xffffffffu, mx1, 1));
        mx1 = fmaxf(mx1, __shfl_xor_sync(0xffffffffu, mx1, 2));

        const float mn0 = fmaxf(m0, mx0), mn1 = fmaxf(m1, mx1);
        const float sc0 = __expf(m0 - mn0), sc1 = __expf(m1 - mn1);
        m0 = mn0; m1 = mn1;

        float ps0 = 0.f, ps1 = 0.f;
#pragma unroll
        for (int nf = 0; nf < 8; nf++) {
            const float p0 = __expf(sacc[nf][0] - mn0);
            const float p1 = __expf(sacc[nf][1] - mn0);
            const float p2 = __expf(sacc[nf][2] - mn1);
            const float p3 = __expf(sacc[nf][3] - mn1);
            ps0 += p0 + p1; ps1 += p2 + p3;
            const int cj = nf * 8 + 2 * q4;
            *(__half2*)(Sc + r0loc * SCP + cj)       = __floats2half2_rn(p0, p1);
            *(__half2*)(Sc + (r0loc + 8) * SCP + cj) = __floats2half2_rn(p2, p3);
        }
        ps0 += __shfl_xor_sync(0xffffffffu, ps0, 1);
        ps0 += __shfl_xor_sync(0xffffffffu, ps0, 2);
        ps1 += __shfl_xor_sync(0xffffffffu, ps1, 1);
        ps1 += __shfl_xor_sync(0xffffffffu, ps1, 2);
        l0 = l0 * sc0 + ps0;
        l1 = l1 * sc1 + ps1;

#pragma unroll
        for (int nf = 0; nf < 16; nf++) {
            o[nf][0] *= sc0; o[nf][1] *= sc0;
            o[nf][2] *= sc1; o[nf][3] *= sc1;
        }
        __syncwarp();

#pragma unroll
        for (int kk = 0; kk < 4; kk++) {
            const int k0 = kk * 16;
            u32 af[4];
            af[0] = *(const u32*)&Sc[r0loc * SCP + k0 + 2 * q4];
            af[1] = *(const u32*)&Sc[(r0loc + 8) * SCP + k0 + 2 * q4];
            af[2] = *(const u32*)&Sc[r0loc * SCP + k0 + 8 + 2 * q4];
            af[3] = *(const u32*)&Sc[(r0loc + 8) * SCP + k0 + 8 + 2 * q4];
            const u32 vrow = k0 + (lane & 15);
            const u32 vcol8 = (lane >> 4) * 8;
#pragma unroll
            for (int nf2 = 0; nf2 < 8; nf2++) {
                u32 b0, b1, b2, b3;
                ldsm_x4_trans(b0, b1, b2, b3,
                              vs_base + (vrow * VP + nf2 * 16 + vcol8) * 2);
                u32 bf0[2] = { b0, b1 };
                u32 bf1[2] = { b2, b3 };
                mma_f16(o[nf2 * 2],     af, bf0);
                mma_f16(o[nf2 * 2 + 1], af, bf1);
            }
        }
        __syncthreads();
    }

    const float inv0 = 1.f / l0, inv1 = 1.f / l1;
    __half* dst0 = g_ctx_h + (size_t)gr0 * H_DIM + h * HD;
    __half* dst1 = g_ctx_h + (size_t)gr1 * H_DIM + h * HD;
#pragma unroll
    for (int nf = 0; nf < 16; nf++) {
        const int d = nf * 8 + 2 * q4;
        *(__half2*)(dst0 + d) = __floats2half2_rn(o[nf][0] * inv0, o[nf][1] * inv0);
        *(__half2*)(dst1 + d) = __floats2half2_rn(o[nf][2] * inv1, o[nf][3] * inv1);
    }
}

// ---------------------------------------------------------------------------
extern "C" void kernel_launch(void* const* d_in, const int* in_sizes, int n_in,
                              void* d_out, int out_size)
{
    const float* hidden  = (const float*)d_in[0];
    const float* resid   = (const float*)d_in[1];
    const float* alibi   = (const float*)d_in[2];
    const float* qkv_w   = (const float*)d_in[4];
    const float* qkv_b   = (const float*)d_in[5];
    const float* dense_w = (const float*)d_in[6];
    const float* dense_b = (const float*)d_in[7];
    float* out = (float*)d_out;

    __half *fused_h, *ctx_h, *hid_h, *qkvw_h, *densew_h;
    cudaGetSymbolAddress((void**)&fused_h, g_fused_h);
    cudaGetSymbolAddress((void**)&ctx_h, g_ctx_h);
    cudaGetSymbolAddress((void**)&hid_h, g_hid_h);
    cudaGetSymbolAddress((void**)&qkvw_h, g_qkvw_h);
    cudaGetSymbolAddress((void**)&densew_h, g_densew_h);

    cudaFuncSetAttribute(gemm_f16<false, true>,
                         cudaFuncAttributeMaxDynamicSharedMemorySize, GEMM_SMEM);
    cudaFuncSetAttribute(gemm_f16<true, false>,
                         cudaFuncAttributeMaxDynamicSharedMemorySize, GEMM_SMEM);
    cudaFuncSetAttribute(attn_mma,
                         cudaFuncAttributeMaxDynamicSharedMemorySize, ATTN_SMEM);

    // 0) Pre-convert inputs/weights to fp16
    {
        const int n4h = (S_LEN * H_DIM) / 4;
        cvt_f16_kernel<<<(n4h + 255) / 256, 256>>>(
            (const float4*)hidden, (uint2*)hid_h, n4h);
        const int n4q = (K3 * H_DIM) / 4;
        cvt_f16_kernel<<<(n4q + 255) / 256, 256>>>(
            (const float4*)qkv_w, (uint2*)qkvw_h, n4q);
        const int n4d = (H_DIM * H_DIM) / 4;
        cvt_f16_kernel<<<(n4d + 255) / 256, 256>>>(
            (const float4*)dense_w, (uint2*)densew_h, n4d);
    }

    // 1) fused = hidden @ qkv_w^T + qkv_b (fp16 mma, half out)
    gemm_f16<false, true><<<dim3(S_LEN / BM, K3 / BN), 256, GEMM_SMEM>>>(
        hid_h, qkvw_h, qkv_b, nullptr, fused_h, S_LEN, K3, H_DIM);

    // 2) attention -> g_ctx_h (half out)
    attn_mma<<<dim3(S_LEN / AQM, NHEADS), 256, ATTN_SMEM>>>(alibi);

    // 3) out = ctx @ dense_w^T + dense_b + residual (fp32 out)
    gemm_f16<true, false><<<dim3(S_LEN / BM, H_DIM / BN), 256, GEMM_SMEM>>>(
        ctx_h, densew_h, dense_b, resid, out, S_LEN, H_DIM, H_DIM);
}

// round 17
// speedup vs baseline: 3.7679x; 1.0162x over previous
#include <cuda_runtime.h>
#include <cuda_fp16.h>
#include <stdint.h>
#include <math.h>

// Problem constants
#define S_LEN   2048
#define H_DIM   4096
#define NHEADS  32
#define HD      128
#define K3      12288            // 3*H
#define INV_NORM 0.08838834764831845f   // 1/sqrt(128)

typedef unsigned int u32;

// Scratch (device globals: allocation-free)
__device__ __half g_fused_h[(size_t)S_LEN * K3];    // [S, NH, 3, HD] half
__device__ __half g_ctx_h[(size_t)S_LEN * H_DIM];   // ctx in half
__device__ __half g_hid_h[(size_t)S_LEN * H_DIM];   // half copy of hidden
__device__ __half g_qkvw_h[(size_t)K3 * H_DIM];     // half copy of qkv_w
__device__ __half g_densew_h[(size_t)H_DIM * H_DIM];// half copy of dense_w

// ---------------------------------------------------------------------------
// Helpers
// ---------------------------------------------------------------------------
__device__ __forceinline__ void mma_f16(float c[4], const u32 a[4],
                                        const u32 b[2]) {
    asm volatile(
        "mma.sync.aligned.m16n8k16.row.col.f32.f16.f16.f32 "
        "{%0,%1,%2,%3}, {%4,%5,%6,%7}, {%8,%9}, {%0,%1,%2,%3};"
        : "+f"(c[0]), "+f"(c[1]), "+f"(c[2]), "+f"(c[3])
        : "r"(a[0]), "r"(a[1]), "r"(a[2]), "r"(a[3]), "r"(b[0]), "r"(b[1]));
}

__device__ __forceinline__ void ldsm_x4(u32& r0, u32& r1, u32& r2, u32& r3,
                                        u32 addr) {
    asm volatile(
        "ldmatrix.sync.aligned.m8n8.x4.shared.b16 {%0,%1,%2,%3}, [%4];"
        : "=r"(r0), "=r"(r1), "=r"(r2), "=r"(r3) : "r"(addr));
}

__device__ __forceinline__ void ldsm_x4_trans(u32& r0, u32& r1, u32& r2,
                                              u32& r3, u32 addr) {
    asm volatile(
        "ldmatrix.sync.aligned.m8n8.x4.trans.shared.b16 {%0,%1,%2,%3}, [%4];"
        : "=r"(r0), "=r"(r1), "=r"(r2), "=r"(r3) : "r"(addr));
}

__device__ __forceinline__ void cpasync16(void* dst_smem, const void* src) {
    u32 sd = (u32)__cvta_generic_to_shared(dst_smem);
    asm volatile("cp.async.cg.shared.global [%0], [%1], 16;"
                 :: "r"(sd), "l"(src));
}

// Elementwise fp32 -> fp16 (rn)
__global__ __launch_bounds__(256) void cvt_f16_kernel(
    const float4* __restrict__ src, uint2* __restrict__ dst, int n4)
{
    const int i = blockIdx.x * blockDim.x + threadIdx.x;
    if (i < n4) {
        float4 v = src[i];
        __half2 h0 = __floats2half2_rn(v.x, v.y);
        __half2 h1 = __floats2half2_rn(v.z, v.w);
        uint2 o;
        o.x = *(u32*)&h0;
        o.y = *(u32*)&h1;
        dst[i] = o;
    }
}

// ---------------------------------------------------------------------------
// fp16 tensor-core GEMM: C = A @ Bw^T + bias (+resid), fp32 accumulate.
// 128x128 CTA, BK=64 halfs (128B rows), 256 threads, warp 64x32.
// 3-stage cp.async pipeline; ldmatrix.x4 on xor-swizzled smem.
// ---------------------------------------------------------------------------
#define BM 128
#define BN 128
#define BKH 64                    // halfs per K-tile row (128 B)
#define TILE_HALFS (BM * BKH)     // 8192 halfs = 16 KB
#define NSTAGE 3
#define GEMM_SMEM (NSTAGE * 2 * TILE_HALFS * 2)   // 98304 B

// swizzled half-offset within a tile: row 128B, chunk = 16B unit
__device__ __forceinline__ int swz(int row, int chunk) {
    return row * BKH + ((chunk ^ (row & 7)) << 3);
}

template<bool ADD_RES, bool HALF_OUT>
__global__ __launch_bounds__(256, 2) void gemm_f16(
    const __half* __restrict__ A, const __half* __restrict__ Bw,
    const float* __restrict__ bias, const float* __restrict__ resid,
    void* __restrict__ Cv, int M, int N, int K)
{
    extern __shared__ __half smh[];

    const int tid  = threadIdx.x;
    const int warp = tid >> 5;
    const int lane = tid & 31;
    const int wm   = (warp & 1) * 64;
    const int wn   = (warp >> 1) * 32;

    const int mt = blockIdx.x;          // M-tile fast -> B tiles L2-resident
    const int nt = blockIdx.y;

    const __half* Ab = A  + (size_t)mt * BM * K;
    const __half* Bb = Bw + (size_t)nt * BN * K;

    // fill thread mapping (constant)
    const int frow = tid >> 3;          // wait no: 256 threads, 1024 chunks
    // each thread does 4 chunks per tile: idx = tid + i*256
    float acc[4][4][4];
#pragma unroll
    for (int i = 0; i < 4; i++)
#pragma unroll
        for (int j = 0; j < 4; j++)
#pragma unroll
            for (int r = 0; r < 4; r++) acc[i][j][r] = 0.f;

    // Prologue: fill stages 0 and 1
#pragma unroll
    for (int s = 0; s < NSTAGE - 1; s++) {
        __half* As = smh + s * 2 * TILE_HALFS;
        __half* Bs = As + TILE_HALFS;
        const int koff = s * BKH;
#pragma unroll
        for (int i = 0; i < 4; i++) {
            const int idx = tid + i * 256;
            const int row = idx >> 3, ch = idx & 7;
            cpasync16(&As[swz(row, ch)], Ab + (size_t)row * K + koff + ch * 8);
            cpasync16(&Bs[swz(row, ch)], Bb + (size_t)row * K + koff + ch * 8);
        }
        asm volatile("cp.async.commit_group;");
    }

    // ldmatrix lane decode (constant per thread)
    const int lmi = lane >> 3;          // matrix index 0..3
    const int lmr = lane & 7;           // row within matrix

    const int NT = K / BKH;
    int buf = 0;
    for (int t = 0; t < NT; t++) {
        // stage t fill was committed as group index t; only the most recent
        // group may remain pending under wait_group 1 (every iter commits).
        asm volatile("cp.async.wait_group 1;");
        __syncthreads();

        // Prefetch stage t+2 into buffer (t+2)%3 (== (t-1)%3, whose readers
        // all passed the barrier above). Always commit (possibly empty).
        if (t + 2 < NT) {
            const int nb = (buf + 2) % NSTAGE;
            __half* An = smh + nb * 2 * TILE_HALFS;
            __half* Bn = An + TILE_HALFS;
            const int koff = (t + 2) * BKH;
#pragma unroll
            for (int i = 0; i < 4; i++) {
                const int idx = tid + i * 256;
                const int row = idx >> 3, ch = idx & 7;
                cpasync16(&An[swz(row, ch)],
                          Ab + (size_t)row * K + koff + ch * 8);
                cpasync16(&Bn[swz(row, ch)],
                          Bb + (size_t)row * K + koff + ch * 8);
            }
        }
        asm volatile("cp.async.commit_group;");

        const u32 as_base =
            (u32)__cvta_generic_to_shared(smh + buf * 2 * TILE_HALFS);
        const u32 bs_base = as_base + TILE_HALFS * 2;

#pragma unroll
        for (int kk = 0; kk < 4; kk++) {
            u32 af[4][4], bf[4][2];
#pragma unroll
            for (int mf = 0; mf < 4; mf++) {
                const int row = wm + mf * 16 + ((lmi & 1) << 3) + lmr;
                const int ch  = 2 * kk + (lmi >> 1);
                ldsm_x4(af[mf][0], af[mf][1], af[mf][2], af[mf][3],
                        as_base + swz(row, ch) * 2);
            }
#pragma unroll
            for (int p = 0; p < 2; p++) {
                const int nf  = 2 * p + (lmi >> 1);
                const int ch  = 2 * kk + (lmi & 1);
                const int row = wn + nf * 8 + lmr;
                u32 b0, b1, b2, b3;
                ldsm_x4(b0, b1, b2, b3, bs_base + swz(row, ch) * 2);
                bf[2 * p][0]     = b0; bf[2 * p][1]     = b1;
                bf[2 * p + 1][0] = b2; bf[2 * p + 1][1] = b3;
            }
#pragma unroll
            for (int mf = 0; mf < 4; mf++)
#pragma unroll
                for (int nf = 0; nf < 4; nf++)
                    mma_f16(acc[mf][nf], af[mf], bf[nf]);
        }

        buf = (buf + 1) % NSTAGE;
    }

#pragma unroll
    for (int mf = 0; mf < 4; mf++) {
        const int row = mt * BM + wm + mf * 16 + (lane >> 2);
#pragma unroll
        for (int nf = 0; nf < 4; nf++) {
            const int col = nt * BN + wn + nf * 8 + 2 * (lane & 3);
            const float b0 = bias[col], b1 = bias[col + 1];
            float v0 = acc[mf][nf][0] + b0;
            float v1 = acc[mf][nf][1] + b1;
            float v2 = acc[mf][nf][2] + b0;
            float v3 = acc[mf][nf][3] + b1;
            if (ADD_RES) {
                v0 += resid[(size_t)row * N + col];
                v1 += resid[(size_t)row * N + col + 1];
                v2 += resid[(size_t)(row + 8) * N + col];
                v3 += resid[(size_t)(row + 8) * N + col + 1];
            }
            if (HALF_OUT) {
                __half* Ch = (__half*)Cv;
                *(__half2*)(Ch + (size_t)row * N + col) =
                    __floats2half2_rn(v0, v1);
                *(__half2*)(Ch + (size_t)(row + 8) * N + col) =
                    __floats2half2_rn(v2, v3);
            } else {
                float* C = (float*)Cv;
                *(float2*)(C + (size_t)row * N + col)       = make_float2(v0, v1);
                *(float2*)(C + (size_t)(row + 8) * N + col) = make_float2(v2, v3);
            }
        }
    }
}

// ---------------------------------------------------------------------------
// fp16 tensor-core flash attention (unchanged from R16, passing).
// ---------------------------------------------------------------------------
#define AQM 128
#define AKT 64
#define QKP 144
#define VP  136
#define SCP 72
#define NEG_INF -1e30f
#define ATTN_SMEM (AQM*QKP*2 + AKT*QKP*2 + AKT*VP*2 + AQM*SCP*2 + S_LEN*4)

__global__ __launch_bounds__(256, 1) void attn_mma(const float* __restrict__ alibi)
{
    extern __shared__ __align__(16) char smraw[];
    __half* Qs  = (__half*)smraw;
    __half* Ks  = Qs + AQM * QKP;
    __half* Vs  = Ks + AKT * QKP;
    __half* Sc  = Vs + AKT * VP;
    float*  sal = (float*)(Sc + AQM * SCP);

    const int qt   = (int)gridDim.x - 1 - (int)blockIdx.x;
    const int q0   = qt * AQM;
    const int h    = blockIdx.y;
    const int tid  = threadIdx.x;
    const int w    = tid >> 5;
    const int lane = tid & 31;
    const int g    = lane >> 2;
    const int q4   = lane & 3;

    const u32 vs_base = (u32)__cvta_generic_to_shared(Vs);

    {
        const __half* qb = g_fused_h + (size_t)q0 * K3 + h * 384;
#pragma unroll
        for (int i = 0; i < 8; i++) {
            const int idx = tid + i * 256;
            const int r = idx >> 4, c8 = (idx & 15) * 8;
            cpasync16(Qs + r * QKP + c8, qb + (size_t)r * K3 + c8);
        }
        asm volatile("cp.async.commit_group;");
        const float* alibi_h = alibi + (size_t)h * S_LEN;
        for (int idx = tid; idx < q0 + AQM; idx += 256)
            sal[idx] = alibi_h[idx];
    }

    const int r0loc = w * 16 + g;
    const int gr0 = q0 + r0loc;
    const int gr1 = gr0 + 8;

    float o[16][4];
#pragma unroll
    for (int nf = 0; nf < 16; nf++)
#pragma unroll
        for (int r = 0; r < 4; r++) o[nf][r] = 0.f;
    float m0 = NEG_INF, m1 = NEG_INF, l0 = 0.f, l1 = 0.f;

    const int nkt = q0 / AKT + 2;
    for (int kt = 0; kt < nkt; kt++) {
        const int kc = kt * AKT;
        {
            const __half* kb = g_fused_h + (size_t)kc * K3 + h * 384 + 128;
#pragma unroll
            for (int i = 0; i < 4; i++) {
                const int idx = tid + i * 256;
                const int r = idx >> 4, c8 = (idx & 15) * 8;
                cpasync16(Ks + r * QKP + c8, kb + (size_t)r * K3 + c8);
                cpasync16(Vs + r * VP + c8, kb + (size_t)r * K3 + 128 + c8);
            }
        }
        asm volatile("cp.async.commit_group;");
        asm volatile("cp.async.wait_group 0;");
        __syncthreads();

        float sacc[8][4];
#pragma unroll
        for (int nf = 0; nf < 8; nf++)
#pragma unroll
            for (int r = 0; r < 4; r++) sacc[nf][r] = 0.f;

#pragma unroll
        for (int kk = 0; kk < 8; kk++) {
            const int kb = kk * 16 + 4 * q4;
            u32 af[4];
            const uint2 x0 = *(const uint2*)&Qs[r0loc * QKP + kb];
            const uint2 x1 = *(const uint2*)&Qs[(r0loc + 8) * QKP + kb];
            af[0] = x0.x; af[1] = x1.x; af[2] = x0.y; af[3] = x1.y;
#pragma unroll
            for (int nf = 0; nf < 8; nf++) {
                const int c0 = nf * 8 + g;
                const uint2 y = *(const uint2*)&Ks[c0 * QKP + kb];
                u32 bf[2];
                bf[0] = y.x; bf[1] = y.y;
                mma_f16(sacc[nf], af, bf);
            }
        }

        float mx0 = NEG_INF, mx1 = NEG_INF;
#pragma unroll
        for (int nf = 0; nf < 8; nf++) {
            const int j0 = kc + nf * 8 + 2 * q4;
            const float a0 = sal[j0], a1 = sal[j0 + 1];
            const float s0 = (j0     <= gr0) ? sacc[nf][0] * INV_NORM + a0 : NEG_INF;
            const float s1 = (j0 + 1 <= gr0) ? sacc[nf][1] * INV_NORM + a1 : NEG_INF;
            const float s2 = (j0     <= gr1) ? sacc[nf][2] * INV_NORM + a0 : NEG_INF;
            const float s3 = (j0 + 1 <= gr1) ? sacc[nf][3] * INV_NORM + a1 : NEG_INF;
            sacc[nf][0] = s0; sacc[nf][1] = s1;
            sacc[nf][2] = s2; sacc[nf][3] = s3;
            mx0 = fmaxf(mx0, fmaxf(s0, s1));
            mx1 = fmaxf(mx1, fmaxf(s2, s3));
        }
        mx0 = fmaxf(mx0, __shfl_xor_sync(0xffffffffu, mx0, 1));
        mx0 = fmaxf(mx0, __shfl_xor_sync(0xffffffffu, mx0, 2));
        mx1 = fmaxf(mx1, __shfl_xor_sync(0xffffffffu, mx1, 1));
        mx1 = fmaxf(mx1, __shfl_xor_sync(0xffffffffu, mx1, 2));

        const float mn0 = fmaxf(m0, mx0), mn1 = fmaxf(m1, mx1);
        const float sc0 = __expf(m0 - mn0), sc1 = __expf(m1 - mn1);
        m0 = mn0; m1 = mn1;

        float ps0 = 0.f, ps1 = 0.f;
#pragma unroll
        for (int nf = 0; nf < 8; nf++) {
            const float p0 = __expf(sacc[nf][0] - mn0);
            const float p1 = __expf(sacc[nf][1] - mn0);
            const float p2 = __expf(sacc[nf][2] - mn1);
            const float p3 = __expf(sacc[nf][3] - mn1);
            ps0 += p0 + p1; ps1 += p2 + p3;
            const int cj = nf * 8 + 2 * q4;
            *(__half2*)(Sc + r0loc * SCP + cj)       = __floats2half2_rn(p0, p1);
            *(__half2*)(Sc + (r0loc + 8) * SCP + cj) = __floats2half2_rn(p2, p3);
        }
        ps0 += __shfl_xor_sync(0xffffffffu, ps0, 1);
        ps0 += __shfl_xor_sync(0xffffffffu, ps0, 2);
        ps1 += __shfl_xor_sync(0xffffffffu, ps1, 1);
        ps1 += __shfl_xor_sync(0xffffffffu, ps1, 2);
        l0 = l0 * sc0 + ps0;
        l1 = l1 * sc1 + ps1;

#pragma unroll
        for (int nf = 0; nf < 16; nf++) {
            o[nf][0] *= sc0; o[nf][1] *= sc0;
            o[nf][2] *= sc1; o[nf][3] *= sc1;
        }
        __syncwarp();

#pragma unroll
        for (int kk = 0; kk < 4; kk++) {
            const int k0 = kk * 16;
            u32 af[4];
            af[0] = *(const u32*)&Sc[r0loc * SCP + k0 + 2 * q4];
            af[1] = *(const u32*)&Sc[(r0loc + 8) * SCP + k0 + 2 * q4];
            af[2] = *(const u32*)&Sc[r0loc * SCP + k0 + 8 + 2 * q4];
            af[3] = *(const u32*)&Sc[(r0loc + 8) * SCP + k0 + 8 + 2 * q4];
            const u32 vrow = k0 + (lane & 15);
            const u32 vcol8 = (lane >> 4) * 8;
#pragma unroll
            for (int nf2 = 0; nf2 < 8; nf2++) {
                u32 b0, b1, b2, b3;
                ldsm_x4_trans(b0, b1, b2, b3,
                              vs_base + (vrow * VP + nf2 * 16 + vcol8) * 2);
                u32 bf0[2] = { b0, b1 };
                u32 bf1[2] = { b2, b3 };
                mma_f16(o[nf2 * 2],     af, bf0);
                mma_f16(o[nf2 * 2 + 1], af, bf1);
            }
        }
        __syncthreads();
    }

    const float inv0 = 1.f / l0, inv1 = 1.f / l1;
    __half* dst0 = g_ctx_h + (size_t)gr0 * H_DIM + h * HD;
    __half* dst1 = g_ctx_h + (size_t)gr1 * H_DIM + h * HD;
#pragma unroll
    for (int nf = 0; nf < 16; nf++) {
        const int d = nf * 8 + 2 * q4;
        *(__half2*)(dst0 + d) = __floats2half2_rn(o[nf][0] * inv0, o[nf][1] * inv0);
        *(__half2*)(dst1 + d) = __floats2half2_rn(o[nf][2] * inv1, o[nf][3] * inv1);
    }
}

// ---------------------------------------------------------------------------
extern "C" void kernel_launch(void* const* d_in, const int* in_sizes, int n_in,
                              void* d_out, int out_size)
{
    const float* hidden  = (const float*)d_in[0];
    const float* resid   = (const float*)d_in[1];
    const float* alibi   = (const float*)d_in[2];
    const float* qkv_w   = (const float*)d_in[4];
    const float* qkv_b   = (const float*)d_in[5];
    const float* dense_w = (const float*)d_in[6];
    const float* dense_b = (const float*)d_in[7];
    float* out = (float*)d_out;

    __half *fused_h, *ctx_h, *hid_h, *qkvw_h, *densew_h;
    cudaGetSymbolAddress((void**)&fused_h, g_fused_h);
    cudaGetSymbolAddress((void**)&ctx_h, g_ctx_h);
    cudaGetSymbolAddress((void**)&hid_h, g_hid_h);
    cudaGetSymbolAddress((void**)&qkvw_h, g_qkvw_h);
    cudaGetSymbolAddress((void**)&densew_h, g_densew_h);

    cudaFuncSetAttribute(gemm_f16<false, true>,
                         cudaFuncAttributeMaxDynamicSharedMemorySize, GEMM_SMEM);
    cudaFuncSetAttribute(gemm_f16<true, false>,
                         cudaFuncAttributeMaxDynamicSharedMemorySize, GEMM_SMEM);
    cudaFuncSetAttribute(attn_mma,
                         cudaFuncAttributeMaxDynamicSharedMemorySize, ATTN_SMEM);

    // 0) Pre-convert inputs/weights to fp16
    {
        const int n4h = (S_LEN * H_DIM) / 4;
        cvt_f16_kernel<<<(n4h + 255) / 256, 256>>>(
            (const float4*)hidden, (uint2*)hid_h, n4h);
        const int n4q = (K3 * H_DIM) / 4;
        cvt_f16_kernel<<<(n4q + 255) / 256, 256>>>(
            (const float4*)qkv_w, (uint2*)qkvw_h, n4q);
        const int n4d = (H_DIM * H_DIM) / 4;
        cvt_f16_kernel<<<(n4d + 255) / 256, 256>>>(
            (const float4*)dense_w, (uint2*)densew_h, n4d);
    }

    // 1) fused = hidden @ qkv_w^T + qkv_b (fp16 mma, half out)
    gemm_f16<false, true><<<dim3(S_LEN / BM, K3 / BN), 256, GEMM_SMEM>>>(
        hid_h, qkvw_h, qkv_b, nullptr, fused_h, S_LEN, K3, H_DIM);

    // 2) attention -> g_ctx_h (half out)
    attn_mma<<<dim3(S_LEN / AQM, NHEADS), 256, ATTN_SMEM>>>(alibi);

    // 3) out = ctx @ dense_w^T + dense_b + residual (fp32 out)
    gemm_f16<true, false><<<dim3(S_LEN / BM, H_DIM / BN), 256, GEMM_SMEM>>>(
        ctx_h, densew_h, dense_b, resid, out, S_LEN, H_DIM, H_DIM);
}